// round 2
// baseline (speedup 1.0000x reference)
#include <cuda_runtime.h>
#include <math.h>

#define NB 8
#define NP 19248
#define MDIM 32
#define TK 200
#define PHW 138
#define IMG 512
#define MIDW 64
#define GSAMP 16
#define GDIM 64
#define EPSV 1e-6f
#define CONF_TH 0.05f
#define NMS_TH 0.5f
#define MAXDET 100

// ------------------------------ scratch ------------------------------------
__device__ float g_conf_k[NB][TK];
__device__ int   g_validk[NB][TK];
__device__ float g_loc_k[NB][TK][4];
__device__ float g_mask_k[NB][TK][MDIM];
__device__ float g_Atab[NB][TK][MIDW];
__device__ float g_Btab[NB][TK][MIDW];
__device__ float g_iou[NB][TK][TK];
__device__ int   g_nkeep[NB];
__device__ int   g_idxG[NB][GSAMP];
__device__ float g_loc_c[NB][TK][4];
__device__ float g_conf_c[NB][TK];
__device__ float g_mask_c[NB][TK][MDIM];
__device__ float g_gy[NB][TK][PHW];
__device__ float g_gx[NB][TK][PHW];
__device__ float g_final[NB][PHW * PHW];
__device__ float g_total[IMG * IMG];
__device__ float g_wmean[3][IMG * IMG];
__device__ float g_losspair[NB][256];
__device__ float g_varpart[1024];

// monotonic encoding: larger float -> larger unsigned
__device__ __forceinline__ unsigned enc_float(float v) {
    unsigned u = __float_as_uint(v);
    return (u & 0x80000000u) ? ~u : (u | 0x80000000u);
}

// ------------------------------ top-k --------------------------------------
__global__ __launch_bounds__(1024) void topk_kernel(const float* __restrict__ conf,
                                                    const float* __restrict__ loc,
                                                    const float* __restrict__ mask) {
    int b = blockIdx.x;
    int tid = threadIdx.x;
    const float* cp = conf + (size_t)b * NP * 2;

    __shared__ unsigned hist[256];
    __shared__ unsigned s_prefix;
    __shared__ int s_remaining;
    __shared__ int s_cnt;
    __shared__ unsigned long long cand[1024];

    if (tid == 0) { s_prefix = 0u; s_remaining = TK; }
    __syncthreads();

    for (int pass = 0; pass < 3; pass++) {
        if (tid < 256) hist[tid] = 0u;
        __syncthreads();
        unsigned prefix = s_prefix;
        int shift_bin = 24 - 8 * pass;
        for (int i = tid; i < NP; i += 1024) {
            float c1 = cp[i * 2 + 1];
            float s = (c1 > CONF_TH) ? c1 : -1.0f;
            unsigned e = enc_float(s);
            unsigned hi = (pass == 0) ? 0u : (e >> (shift_bin + 8));
            if (hi == prefix) atomicAdd(&hist[(e >> shift_bin) & 0xFFu], 1u);
        }
        __syncthreads();
        if (tid == 0) {
            int rem = s_remaining;
            unsigned cum = 0;
            for (int x = 255; x >= 0; x--) {
                unsigned h = hist[x];
                if (cum + h >= (unsigned)rem) {
                    s_remaining = rem - (int)cum;
                    s_prefix = (s_prefix << 8) | (unsigned)x;
                    break;
                }
                cum += h;
            }
        }
        __syncthreads();
    }

    if (tid == 0) s_cnt = 0;
    __syncthreads();
    unsigned thr24 = s_prefix;
    for (int i = tid; i < NP; i += 1024) {
        float c1 = cp[i * 2 + 1];
        float s = (c1 > CONF_TH) ? c1 : -1.0f;
        unsigned e = enc_float(s);
        if ((e >> 8) >= thr24) {
            int pos = atomicAdd(&s_cnt, 1);
            if (pos < 1024)
                cand[pos] = ((unsigned long long)e << 32) |
                            (unsigned long long)(0xFFFFFFFFu - (unsigned)i);
        }
    }
    __syncthreads();
    int cnt = s_cnt;
    if (cnt > 1024) cnt = 1024;
    if (tid >= cnt) cand[tid] = 0ull;
    __syncthreads();

    // bitonic sort descending (1024 elems, 1024 threads)
    for (int k = 2; k <= 1024; k <<= 1) {
        for (int j = k >> 1; j > 0; j >>= 1) {
            int i = tid;
            int ixj = i ^ j;
            if (ixj > i) {
                unsigned long long a = cand[i], c = cand[ixj];
                bool descSeg = ((i & k) == 0);
                bool swap = descSeg ? (a < c) : (a > c);
                if (swap) { cand[i] = c; cand[ixj] = a; }
            }
            __syncthreads();
        }
    }

    if (tid < TK) {
        unsigned long long key = cand[tid];
        unsigned e = (unsigned)(key >> 32);
        int idx = (int)(0xFFFFFFFFu - (unsigned)(key & 0xFFFFFFFFull));
        unsigned u = (e & 0x80000000u) ? (e ^ 0x80000000u) : ~e;
        float v = __uint_as_float(u);
        int val = (v > CONF_TH) ? 1 : 0;
        g_validk[b][tid] = val;
        g_conf_k[b][tid] = val ? v : 0.0f;
        const float* lp = loc + ((size_t)b * NP + idx) * 4;
#pragma unroll
        for (int d = 0; d < 4; d++) g_loc_k[b][tid][d] = lp[d];
        const float* mp = mask + ((size_t)b * NP + idx) * MDIM;
#pragma unroll
        for (int d = 0; d < MDIM; d++) g_mask_k[b][tid][d] = mp[d];
    }
}

// ------------------------ MLP factor tables --------------------------------
__global__ void tables_kernel(const float* __restrict__ W1, const float* __restrict__ b1) {
    int t = blockIdx.x * blockDim.x + threadIdx.x;
    if (t >= NB * TK * MIDW) return;
    int h = t % MIDW;
    int k = (t / MIDW) % TK;
    int b = t / (MIDW * TK);
    float l0 = g_loc_k[b][k][0], l1 = g_loc_k[b][k][1];
    float l2 = g_loc_k[b][k][2], l3 = g_loc_k[b][k][3];
    float a = fmaf(l3, W1[3 * MIDW + h],
              fmaf(l2, W1[2 * MIDW + h],
              fmaf(l1, W1[1 * MIDW + h], l0 * W1[h])));
    float bb = fmaf(l3, W1[7 * MIDW + h],
               fmaf(l2, W1[6 * MIDW + h],
               fmaf(l1, W1[5 * MIDW + h], l0 * W1[4 * MIDW + h]))) + b1[h];
    g_Atab[b][k][h] = a;
    g_Btab[b][k][h] = bb;
}

// -------------------------- 200x200 IoU MLP --------------------------------
__global__ void mlp_kernel(const float* __restrict__ W2, const float* __restrict__ b2) {
    int b = blockIdx.z;
    int jb = blockIdx.x * 16, ib = blockIdx.y * 16;
    __shared__ float As[16][MIDW + 1];
    __shared__ float Bs[16][MIDW + 1];
    __shared__ float w2s[MIDW];
    __shared__ float s_b2;
    int tid = threadIdx.x;
    for (int t = tid; t < 16 * MIDW; t += 256) {
        int r = t / MIDW, h = t % MIDW;
        As[r][h] = (jb + r < TK) ? g_Atab[b][jb + r][h] : 0.0f;
        Bs[r][h] = (ib + r < TK) ? g_Btab[b][ib + r][h] : 0.0f;
    }
    if (tid < MIDW) w2s[tid] = W2[tid];
    if (tid == 0) s_b2 = b2[0];
    __syncthreads();
    int tj = tid & 15, ti = tid >> 4;
    int i = ib + ti, j = jb + tj;
    if (i < TK && j < TK) {
        float acc = s_b2;
#pragma unroll
        for (int h = 0; h < MIDW; h++) {
            float s = As[tj][h] + Bs[ti][h];
            acc = fmaf(fmaxf(s, 0.0f), w2s[h], acc);
        }
        g_iou[b][i][j] = 1.0f / (1.0f + expf(-acc));
    }
}

// ------------------------------- NMS ---------------------------------------
__global__ void nms_kernel() {
    int b = blockIdx.x, tid = threadIdx.x;
    __shared__ int s_valid[TK];
    __shared__ int s_keep[TK];
    __shared__ int s_perm[TK];
    __shared__ int s_nk;
    if (tid < TK) s_valid[tid] = g_validk[b][tid];
    __syncthreads();
    if (tid < TK) {
        int kp = 0;
        if (s_valid[tid]) {
            float m = 0.0f;
            for (int i = 0; i < tid; i++)
                if (s_valid[i]) m = fmaxf(m, g_iou[b][i][tid]);
            kp = (m <= NMS_TH) ? 1 : 0;
        }
        s_keep[tid] = kp;
    }
    __syncthreads();
    if (tid == 0) {
        int cnt = 0;
        for (int j = 0; j < TK; j++) {
            if (s_keep[j]) {
                if (cnt < MAXDET) cnt++;
                else s_keep[j] = 0;
            }
        }
        int pos = 0;
        for (int j = 0; j < TK; j++) if (s_keep[j]) s_perm[pos++] = j;
        for (int j = 0; j < TK; j++) if (!s_keep[j]) s_perm[pos++] = j;
        s_nk = cnt;
        g_nkeep[b] = cnt;
    }
    __syncthreads();
    int nk = s_nk;
    if (tid < TK) {
        int p = s_perm[tid];
        float kc = (tid < nk) ? 1.0f : 0.0f;
#pragma unroll
        for (int d = 0; d < 4; d++) g_loc_c[b][tid][d] = g_loc_k[b][p][d];
        g_conf_c[b][tid] = g_conf_k[b][p] * kc;
#pragma unroll
        for (int d = 0; d < MDIM; d++) g_mask_c[b][tid][d] = g_mask_k[b][p][d] * kc;
    }
    if (tid < GSAMP) g_idxG[b][tid] = s_perm[tid];
}

// --------------------------- gaussian IoU loss -----------------------------
__global__ void loss_kernel() {
    int b = blockIdx.y;
    int pr = blockIdx.x;  // 0..255
    int p = pr >> 4, q = pr & 15;
    int tid = threadIdx.x;
    __shared__ float gyp[GDIM], gxp[GDIM], gyq[GDIM], gxq[GDIM];
    __shared__ float ri[4], ru[4];
    int g = min(GSAMP, g_nkeep[b]);
    float result = 0.0f;
    if (p < g && q < g) {
        float cxp = g_loc_c[b][p][0], cyp = g_loc_c[b][p][1];
        float bwp = g_loc_c[b][p][2], bhp = g_loc_c[b][p][3];
        float cxq = g_loc_c[b][q][0], cyq = g_loc_c[b][q][1];
        float bwq = g_loc_c[b][q][2], bhq = g_loc_c[b][q][3];
        if (tid < GDIM) {
            float s = (tid + 0.5f) / (float)GDIM;
            float ty = (s - cyp) / (bhp * 0.5f + EPSV); gyp[tid] = expf(-0.5f * ty * ty);
            float tx = (s - cxp) / (bwp * 0.5f + EPSV); gxp[tid] = expf(-0.5f * tx * tx);
            float uy = (s - cyq) / (bhq * 0.5f + EPSV); gyq[tid] = expf(-0.5f * uy * uy);
            float ux = (s - cxq) / (bwq * 0.5f + EPSV); gxq[tid] = expf(-0.5f * ux * ux);
        }
        __syncthreads();
        float inter = 0.0f, uni = 0.0f;
        for (int pix = tid; pix < GDIM * GDIM; pix += blockDim.x) {
            int y = pix >> 6, x = pix & 63;
            float a = gyp[y] * gxp[x];
            float c = gyq[y] * gxq[x];
            inter += fminf(a, c);
            uni += fmaxf(a, c);
        }
        for (int o = 16; o > 0; o >>= 1) {
            inter += __shfl_down_sync(0xFFFFFFFFu, inter, o);
            uni   += __shfl_down_sync(0xFFFFFFFFu, uni, o);
        }
        int w = tid >> 5;
        if ((tid & 31) == 0) { ri[w] = inter; ru[w] = uni; }
        __syncthreads();
        if (tid == 0) {
            float I = ri[0] + ri[1] + ri[2] + ri[3];
            float U = ru[0] + ru[1] + ru[2] + ru[3];
            float giou = I / (U + EPSV);
            float pred = g_iou[b][g_idxG[b][p]][g_idxG[b][q]];
            float d = pred - giou;
            result = d * d;
        }
    }
    if (tid == 0) g_losspair[b][pr] = result;
}

// ----------------------- gaussian tables for attention ---------------------
__global__ void gauss_kernel() {
    int k = blockIdx.x, b = blockIdx.y;
    if (k >= g_nkeep[b]) return;
    int t = threadIdx.x;
    if (t < PHW) {
        float cx = g_loc_c[b][k][0], cy = g_loc_c[b][k][1];
        float bw = g_loc_c[b][k][2], bh = g_loc_c[b][k][3];
        float s = (t + 0.5f) / (float)PHW;
        float ty = (s - cy) / (bh * 0.5f + EPSV);
        float tx = (s - cx) / (bw * 0.5f + EPSV);
        g_gy[b][k][t] = expf(-0.5f * ty * ty);
        g_gx[b][k][t] = expf(-0.5f * tx * tx);
    }
}

// -------------------- attention / final 138x138 map ------------------------
__global__ __launch_bounds__(256) void attn_kernel(const float* __restrict__ proto) {
    int b = blockIdx.y;
    int tid = threadIdx.x;
    int nk = g_nkeep[b];
    __shared__ float s_mask[MAXDET * MDIM];
    __shared__ float s_conf[MAXDET];
    for (int t = tid; t < nk * MDIM; t += 256)
        s_mask[t] = g_mask_c[b][t / MDIM][t % MDIM];
    for (int t = tid; t < nk; t += 256) s_conf[t] = g_conf_c[b][t];
    __syncthreads();
    int p = blockIdx.x * 256 + tid;
    if (p >= PHW * PHW) return;
    int y = p / PHW, x = p % PHW;
    const float4* pp =
        reinterpret_cast<const float4*>(proto + (((size_t)b * PHW + y) * PHW + x) * MDIM);
    float4 pr[8];
#pragma unroll
    for (int i = 0; i < 8; i++) pr[i] = pp[i];
    float s1 = 0.0f, s2 = 0.0f;
    const float* gyb = &g_gy[b][0][0];
    const float* gxb = &g_gx[b][0][0];
    for (int k = 0; k < nk; k++) {
        const float4* mk = reinterpret_cast<const float4*>(&s_mask[k * MDIM]);
        float dot = 0.0f;
#pragma unroll
        for (int i = 0; i < 8; i++) {
            float4 m = mk[i];
            dot = fmaf(pr[i].x, m.x, dot);
            dot = fmaf(pr[i].y, m.y, dot);
            dot = fmaf(pr[i].z, m.z, dot);
            dot = fmaf(pr[i].w, m.w, dot);
        }
        float sg = 1.0f / (1.0f + expf(-dot));
        float mv = sg * __ldg(gyb + k * PHW + y) * __ldg(gxb + k * PHW + x) * s_conf[k];
        s1 += mv;
        s2 = fmaf(mv, mv, s2);
    }
    g_final[b][p] = 1.0f - s2 / (s1 + EPSV);
}

// --------------------- resize + total/wmean (pass 1) -----------------------
__device__ __forceinline__ void resize_coords(int y, int x, int& y0, int& y1,
                                              int& x0, int& x1, float& wy, float& wx) {
    const float S = (float)PHW / (float)IMG;
    float sy = (y + 0.5f) * S - 0.5f;
    float sx = (x + 0.5f) * S - 0.5f;
    float fy = floorf(sy), fx = floorf(sx);
    wy = sy - fy;
    wx = sx - fx;
    y0 = max((int)fy, 0); y1 = min((int)fy + 1, PHW - 1);
    x0 = max((int)fx, 0); x1 = min((int)fx + 1, PHW - 1);
}

__device__ __forceinline__ float bilerp(const float* fb, int y0, int y1, int x0,
                                        int x1, float wy, float wx) {
    float a = fb[y0 * PHW + x0], b = fb[y0 * PHW + x1];
    float c = fb[y1 * PHW + x0], d = fb[y1 * PHW + x1];
    float top = a + (b - a) * wx;
    float bot = c + (d - c) * wx;
    return top + (bot - top) * wy;
}

__global__ __launch_bounds__(256) void resize_stat_kernel(const float* __restrict__ original) {
    int p = blockIdx.x * blockDim.x + threadIdx.x;
    if (p >= IMG * IMG) return;
    int y = p >> 9, x = p & 511;
    int y0, y1, x0, x1; float wy, wx;
    resize_coords(y, x, y0, y1, x0, x1, wy, wx);
    float tot = 0.0f, wm0 = 0.0f, wm1 = 0.0f, wm2 = 0.0f;
#pragma unroll
    for (int b = 0; b < NB; b++) {
        float r = bilerp(g_final[b], y0, y1, x0, x1, wy, wx);
        tot += r;
        size_t base = ((size_t)b * 3) * (IMG * IMG) + p;
        wm0 = fmaf(original[base], r, wm0);
        wm1 = fmaf(original[base + IMG * IMG], r, wm1);
        wm2 = fmaf(original[base + 2 * IMG * IMG], r, wm2);
    }
    g_total[p] = tot;
    g_wmean[0][p] = wm0;
    g_wmean[1][p] = wm1;
    g_wmean[2][p] = wm2;
}

// ----------------------- weighted variance (pass 2) ------------------------
__global__ __launch_bounds__(256) void var_kernel(const float* __restrict__ original) {
    int p = blockIdx.x * blockDim.x + threadIdx.x;
    int tid = threadIdx.x;
    float acc = 0.0f;
    if (p < IMG * IMG) {
        int y = p >> 9, x = p & 511;
        int y0, y1, x0, x1; float wy, wx;
        resize_coords(y, x, y0, y1, x0, x1, wy, wx);
        float tinv = 1.0f / (g_total[p] + EPSV);
        float wm0 = g_wmean[0][p], wm1 = g_wmean[1][p], wm2 = g_wmean[2][p];
#pragma unroll
        for (int b = 0; b < NB; b++) {
            float r = bilerp(g_final[b], y0, y1, x0, x1, wy, wx);
            size_t base = ((size_t)b * 3) * (IMG * IMG) + p;
            float d0 = original[base] - wm0;
            float d1 = original[base + IMG * IMG] - wm1;
            float d2 = original[base + 2 * IMG * IMG] - wm2;
            acc = fmaf((d0 * d0 + d1 * d1 + d2 * d2), r, acc);
        }
        acc *= tinv;
    }
    // block reduce (256 threads)
    for (int o = 16; o > 0; o >>= 1) acc += __shfl_down_sync(0xFFFFFFFFu, acc, o);
    __shared__ float rs[8];
    int w = tid >> 5;
    if ((tid & 31) == 0) rs[w] = acc;
    __syncthreads();
    if (tid == 0) {
        float s = 0.0f;
#pragma unroll
        for (int i = 0; i < 8; i++) s += rs[i];
        g_varpart[blockIdx.x] = s;
    }
}

// ------------------------------ finalize -----------------------------------
__global__ void finalize_kernel(float* __restrict__ out) {
    __shared__ double sm[256];
    int tid = threadIdx.x;
    double a = 0.0;
    for (int i = tid; i < 1024; i += 256) a += (double)g_varpart[i];
    sm[tid] = a;
    __syncthreads();
    for (int s = 128; s > 0; s >>= 1) {
        if (tid < s) sm[tid] += sm[tid + s];
        __syncthreads();
    }
    if (tid == 0) out[0] = (float)sm[0];
    __syncthreads();
    double l = 0.0;
    const float* lp = &g_losspair[0][0];
    for (int i = tid; i < NB * 256; i += 256) l += (double)lp[i];
    sm[tid] = l;
    __syncthreads();
    for (int s = 128; s > 0; s >>= 1) {
        if (tid < s) sm[tid] += sm[tid + s];
        __syncthreads();
    }
    if (tid == 0) out[1] = (float)sm[0];
}

// ------------------------------ launcher -----------------------------------
extern "C" void kernel_launch(void* const* d_in, const int* in_sizes, int n_in,
                              void* d_out, int out_size) {
    const float* original = (const float*)d_in[0];
    const float* loc      = (const float*)d_in[1];
    const float* conf     = (const float*)d_in[2];
    const float* mask     = (const float*)d_in[3];
    const float* proto    = (const float*)d_in[4];
    const float* W1       = (const float*)d_in[5];
    const float* b1       = (const float*)d_in[6];
    const float* W2       = (const float*)d_in[7];
    const float* b2       = (const float*)d_in[8];
    float* out = (float*)d_out;

    topk_kernel<<<NB, 1024>>>(conf, loc, mask);
    tables_kernel<<<(NB * TK * MIDW + 255) / 256, 256>>>(W1, b1);
    mlp_kernel<<<dim3((TK + 15) / 16, (TK + 15) / 16, NB), 256>>>(W2, b2);
    nms_kernel<<<NB, 256>>>();
    loss_kernel<<<dim3(256, NB), 128>>>();
    gauss_kernel<<<dim3(TK, NB), 160>>>();
    attn_kernel<<<dim3((PHW * PHW + 255) / 256, NB), 256>>>(proto);
    resize_stat_kernel<<<(IMG * IMG) / 256, 256>>>(original);
    var_kernel<<<(IMG * IMG) / 256, 256>>>(original);
    finalize_kernel<<<1, 256>>>(out);
}

// round 3
// speedup vs baseline: 1.3948x; 1.3948x over previous
#include <cuda_runtime.h>
#include <math.h>

#define NB 8
#define NP 19248
#define MDIM 32
#define TK 200
#define PHW 138
#define IMG 512
#define MIDW 64
#define GSAMP 16
#define GDIM 64
#define EPSV 1e-6f
#define CONF_TH 0.05f
#define NMS_TH 0.5f
#define MAXDET 100

// ------------------------------ scratch ------------------------------------
__device__ float g_conf_k[NB][TK];
__device__ int   g_validk[NB][TK];
__device__ float g_loc_k[NB][TK][4];
__device__ float g_mask_k[NB][TK][MDIM];
__device__ float g_Atab[NB][TK][MIDW];
__device__ float g_Btab[NB][TK][MIDW];
__device__ float g_iou[NB][TK][TK];
__device__ int   g_ioumaxI[NB][TK];
__device__ int   g_nkeep[NB];
__device__ int   g_idxG[NB][GSAMP];
__device__ float g_loc_c[NB][TK][4];
__device__ float g_conf_c[NB][TK];
__device__ float g_mask_c[NB][TK][MDIM];
__device__ float g_gy[NB][TK][PHW];
__device__ float g_gx[NB][TK][PHW];
__device__ float g_final[NB][PHW * PHW];
__device__ float g_losspair[NB][256];
__device__ float g_varpart[1024];

// monotonic encoding: larger float -> larger unsigned
__device__ __forceinline__ unsigned enc_float(float v) {
    unsigned u = __float_as_uint(v);
    return (u & 0x80000000u) ? ~u : (u | 0x80000000u);
}

// ------------------------------ top-k --------------------------------------
__global__ __launch_bounds__(1024) void topk_kernel(const float* __restrict__ conf,
                                                    const float* __restrict__ loc,
                                                    const float* __restrict__ mask) {
    int b = blockIdx.x;
    int tid = threadIdx.x;
    const float* cp = conf + (size_t)b * NP * 2;

    __shared__ unsigned hist[256];
    __shared__ unsigned s_prefix;
    __shared__ int s_remaining;
    __shared__ int s_cnt;
    __shared__ unsigned long long cand[1024];

    if (tid == 0) { s_prefix = 0u; s_remaining = TK; }
    __syncthreads();

    for (int pass = 0; pass < 3; pass++) {
        if (tid < 256) hist[tid] = 0u;
        __syncthreads();
        unsigned prefix = s_prefix;
        int shift_bin = 24 - 8 * pass;
        for (int i = tid; i < NP; i += 1024) {
            float c1 = cp[i * 2 + 1];
            float s = (c1 > CONF_TH) ? c1 : -1.0f;
            unsigned e = enc_float(s);
            unsigned hi = (pass == 0) ? 0u : (e >> (shift_bin + 8));
            if (hi == prefix) atomicAdd(&hist[(e >> shift_bin) & 0xFFu], 1u);
        }
        __syncthreads();
        if (tid == 0) {
            int rem = s_remaining;
            unsigned cum = 0;
            for (int x = 255; x >= 0; x--) {
                unsigned h = hist[x];
                if (cum + h >= (unsigned)rem) {
                    s_remaining = rem - (int)cum;
                    s_prefix = (s_prefix << 8) | (unsigned)x;
                    break;
                }
                cum += h;
            }
        }
        __syncthreads();
    }

    if (tid == 0) s_cnt = 0;
    __syncthreads();
    unsigned thr24 = s_prefix;
    for (int i = tid; i < NP; i += 1024) {
        float c1 = cp[i * 2 + 1];
        float s = (c1 > CONF_TH) ? c1 : -1.0f;
        unsigned e = enc_float(s);
        if ((e >> 8) >= thr24) {
            int pos = atomicAdd(&s_cnt, 1);
            if (pos < 1024)
                cand[pos] = ((unsigned long long)e << 32) |
                            (unsigned long long)(0xFFFFFFFFu - (unsigned)i);
        }
    }
    __syncthreads();
    int cnt = s_cnt;
    if (cnt > 1024) cnt = 1024;
    if (tid >= cnt) cand[tid] = 0ull;
    __syncthreads();

    // bitonic sort descending (1024 elems, 1024 threads)
    for (int k = 2; k <= 1024; k <<= 1) {
        for (int j = k >> 1; j > 0; j >>= 1) {
            int i = tid;
            int ixj = i ^ j;
            if (ixj > i) {
                unsigned long long a = cand[i], c = cand[ixj];
                bool descSeg = ((i & k) == 0);
                bool swap = descSeg ? (a < c) : (a > c);
                if (swap) { cand[i] = c; cand[ixj] = a; }
            }
            __syncthreads();
        }
    }

    if (tid < TK) {
        unsigned long long key = cand[tid];
        unsigned e = (unsigned)(key >> 32);
        int idx = (int)(0xFFFFFFFFu - (unsigned)(key & 0xFFFFFFFFull));
        unsigned u = (e & 0x80000000u) ? (e ^ 0x80000000u) : ~e;
        float v = __uint_as_float(u);
        int val = (v > CONF_TH) ? 1 : 0;
        g_validk[b][tid] = val;
        g_conf_k[b][tid] = val ? v : 0.0f;
        g_ioumaxI[b][tid] = 0;   // init for mlp's atomicMax
        const float* lp = loc + ((size_t)b * NP + idx) * 4;
#pragma unroll
        for (int d = 0; d < 4; d++) g_loc_k[b][tid][d] = lp[d];
        const float* mp = mask + ((size_t)b * NP + idx) * MDIM;
#pragma unroll
        for (int d = 0; d < MDIM; d++) g_mask_k[b][tid][d] = mp[d];
    }
}

// ------------------------ MLP factor tables --------------------------------
__global__ void tables_kernel(const float* __restrict__ W1, const float* __restrict__ b1) {
    int t = blockIdx.x * blockDim.x + threadIdx.x;
    if (t >= NB * TK * MIDW) return;
    int h = t % MIDW;
    int k = (t / MIDW) % TK;
    int b = t / (MIDW * TK);
    float l0 = g_loc_k[b][k][0], l1 = g_loc_k[b][k][1];
    float l2 = g_loc_k[b][k][2], l3 = g_loc_k[b][k][3];
    float a = fmaf(l3, W1[3 * MIDW + h],
              fmaf(l2, W1[2 * MIDW + h],
              fmaf(l1, W1[1 * MIDW + h], l0 * W1[h])));
    float bb = fmaf(l3, W1[7 * MIDW + h],
               fmaf(l2, W1[6 * MIDW + h],
               fmaf(l1, W1[5 * MIDW + h], l0 * W1[4 * MIDW + h]))) + b1[h];
    g_Atab[b][k][h] = a;
    g_Btab[b][k][h] = bb;
}

// -------------------------- 200x200 IoU MLP + column max -------------------
__global__ void mlp_kernel(const float* __restrict__ W2, const float* __restrict__ b2) {
    int b = blockIdx.z;
    int jb = blockIdx.x * 16, ib = blockIdx.y * 16;
    __shared__ float As[16][MIDW + 1];
    __shared__ float Bs[16][MIDW + 1];
    __shared__ float w2s[MIDW];
    __shared__ float s_b2;
    __shared__ int s_vi[16], s_vj[16];
    int tid = threadIdx.x;
    for (int t = tid; t < 16 * MIDW; t += 256) {
        int r = t / MIDW, h = t % MIDW;
        As[r][h] = (jb + r < TK) ? g_Atab[b][jb + r][h] : 0.0f;
        Bs[r][h] = (ib + r < TK) ? g_Btab[b][ib + r][h] : 0.0f;
    }
    if (tid < MIDW) w2s[tid] = W2[tid];
    if (tid == 0) s_b2 = b2[0];
    if (tid < 16) {
        s_vj[tid] = (jb + tid < TK) ? g_validk[b][jb + tid] : 0;
        s_vi[tid] = (ib + tid < TK) ? g_validk[b][ib + tid] : 0;
    }
    __syncthreads();
    int tj = tid & 15, ti = tid >> 4;
    int i = ib + ti, j = jb + tj;
    if (i < TK && j < TK) {
        float acc = s_b2;
#pragma unroll
        for (int h = 0; h < MIDW; h++) {
            float s = As[tj][h] + Bs[ti][h];
            acc = fmaf(fmaxf(s, 0.0f), w2s[h], acc);
        }
        float iou = 1.0f / (1.0f + expf(-acc));
        g_iou[b][i][j] = iou;
        // masked column max for fast-NMS: max over i<j, both valid
        if (i < j && s_vi[ti] && s_vj[tj])
            atomicMax(&g_ioumaxI[b][j], __float_as_int(iou));
    }
}

// ------------------------------- NMS (scan-based) --------------------------
__global__ __launch_bounds__(256) void nms_kernel() {
    int b = blockIdx.x, tid = threadIdx.x;
    __shared__ int s_scan[256];
    __shared__ int s_perm[TK];
    int keep = 0;
    if (tid < TK) {
        int valid = g_validk[b][tid];
        float m = __int_as_float(g_ioumaxI[b][tid]);
        keep = (valid && m <= NMS_TH) ? 1 : 0;
    }
    s_scan[tid] = keep;
    __syncthreads();
    // Hillis-Steele inclusive scan over 256
#pragma unroll
    for (int off = 1; off < 256; off <<= 1) {
        int v = s_scan[tid];
        int add = (tid >= off) ? s_scan[tid - off] : 0;
        __syncthreads();
        s_scan[tid] = v + add;
        __syncthreads();
    }
    int incl = s_scan[tid];
    int nk = min(s_scan[TK - 1], MAXDET);
    int keep2 = keep && (incl <= MAXDET);
    int incl2 = min(incl, MAXDET);
    if (tid == 0) g_nkeep[b] = nk;
    if (tid < TK) {
        int pos = keep2 ? (incl2 - 1) : (nk + tid - incl2);
        s_perm[pos] = tid;
    }
    __syncthreads();
    if (tid < TK) {
        int p = s_perm[tid];
        float kc = (tid < nk) ? 1.0f : 0.0f;
#pragma unroll
        for (int d = 0; d < 4; d++) g_loc_c[b][tid][d] = g_loc_k[b][p][d];
        g_conf_c[b][tid] = g_conf_k[b][p] * kc;
#pragma unroll
        for (int d = 0; d < MDIM; d++) g_mask_c[b][tid][d] = g_mask_k[b][p][d] * kc;
    }
    if (tid < GSAMP) g_idxG[b][tid] = s_perm[tid];
}

// --------------------------- gaussian IoU loss -----------------------------
__global__ void loss_kernel() {
    int b = blockIdx.y;
    int pr = blockIdx.x;  // 0..255
    int p = pr >> 4, q = pr & 15;
    int tid = threadIdx.x;
    __shared__ float gyp[GDIM], gxp[GDIM], gyq[GDIM], gxq[GDIM];
    __shared__ float ri[4], ru[4];
    int g = min(GSAMP, g_nkeep[b]);
    float result = 0.0f;
    if (p < g && q < g) {
        float cxp = g_loc_c[b][p][0], cyp = g_loc_c[b][p][1];
        float bwp = g_loc_c[b][p][2], bhp = g_loc_c[b][p][3];
        float cxq = g_loc_c[b][q][0], cyq = g_loc_c[b][q][1];
        float bwq = g_loc_c[b][q][2], bhq = g_loc_c[b][q][3];
        if (tid < GDIM) {
            float s = (tid + 0.5f) / (float)GDIM;
            float ty = (s - cyp) / (bhp * 0.5f + EPSV); gyp[tid] = expf(-0.5f * ty * ty);
            float tx = (s - cxp) / (bwp * 0.5f + EPSV); gxp[tid] = expf(-0.5f * tx * tx);
            float uy = (s - cyq) / (bhq * 0.5f + EPSV); gyq[tid] = expf(-0.5f * uy * uy);
            float ux = (s - cxq) / (bwq * 0.5f + EPSV); gxq[tid] = expf(-0.5f * ux * ux);
        }
        __syncthreads();
        float inter = 0.0f, uni = 0.0f;
        for (int pix = tid; pix < GDIM * GDIM; pix += blockDim.x) {
            int y = pix >> 6, x = pix & 63;
            float a = gyp[y] * gxp[x];
            float c = gyq[y] * gxq[x];
            inter += fminf(a, c);
            uni += fmaxf(a, c);
        }
        for (int o = 16; o > 0; o >>= 1) {
            inter += __shfl_down_sync(0xFFFFFFFFu, inter, o);
            uni   += __shfl_down_sync(0xFFFFFFFFu, uni, o);
        }
        int w = tid >> 5;
        if ((tid & 31) == 0) { ri[w] = inter; ru[w] = uni; }
        __syncthreads();
        if (tid == 0) {
            float I = ri[0] + ri[1] + ri[2] + ri[3];
            float U = ru[0] + ru[1] + ru[2] + ru[3];
            float giou = I / (U + EPSV);
            float pred = g_iou[b][g_idxG[b][p]][g_idxG[b][q]];
            float d = pred - giou;
            result = d * d;
        }
    }
    if (tid == 0) g_losspair[b][pr] = result;
}

// ----------------------- gaussian tables for attention ---------------------
__global__ void gauss_kernel() {
    int k = blockIdx.x, b = blockIdx.y;
    if (k >= g_nkeep[b]) return;
    int t = threadIdx.x;
    if (t < PHW) {
        float cx = g_loc_c[b][k][0], cy = g_loc_c[b][k][1];
        float bw = g_loc_c[b][k][2], bh = g_loc_c[b][k][3];
        float s = (t + 0.5f) / (float)PHW;
        float ty = (s - cy) / (bh * 0.5f + EPSV);
        float tx = (s - cx) / (bw * 0.5f + EPSV);
        g_gy[b][k][t] = expf(-0.5f * ty * ty);
        g_gx[b][k][t] = expf(-0.5f * tx * tx);
    }
}

// -------------------- attention / final 138x138 map ------------------------
__global__ __launch_bounds__(256) void attn_kernel(const float* __restrict__ proto) {
    int b = blockIdx.y;
    int tid = threadIdx.x;
    int nk = g_nkeep[b];
    __shared__ float s_mask[MAXDET * MDIM];
    __shared__ float s_conf[MAXDET];
    for (int t = tid; t < nk * MDIM; t += 256)
        s_mask[t] = g_mask_c[b][t / MDIM][t % MDIM];
    for (int t = tid; t < nk; t += 256) s_conf[t] = g_conf_c[b][t];
    __syncthreads();
    int p = blockIdx.x * 256 + tid;
    if (p >= PHW * PHW) return;
    int y = p / PHW, x = p % PHW;
    const float4* pp =
        reinterpret_cast<const float4*>(proto + (((size_t)b * PHW + y) * PHW + x) * MDIM);
    float4 pr[8];
#pragma unroll
    for (int i = 0; i < 8; i++) pr[i] = pp[i];
    float s1 = 0.0f, s2 = 0.0f;
    const float* gyb = &g_gy[b][0][0];
    const float* gxb = &g_gx[b][0][0];
    for (int k = 0; k < nk; k++) {
        const float4* mk = reinterpret_cast<const float4*>(&s_mask[k * MDIM]);
        float dot = 0.0f;
#pragma unroll
        for (int i = 0; i < 8; i++) {
            float4 m = mk[i];
            dot = fmaf(pr[i].x, m.x, dot);
            dot = fmaf(pr[i].y, m.y, dot);
            dot = fmaf(pr[i].z, m.z, dot);
            dot = fmaf(pr[i].w, m.w, dot);
        }
        float sg = 1.0f / (1.0f + expf(-dot));
        float mv = sg * __ldg(gyb + k * PHW + y) * __ldg(gxb + k * PHW + x) * s_conf[k];
        s1 += mv;
        s2 = fmaf(mv, mv, s2);
    }
    g_final[b][p] = 1.0f - s2 / (s1 + EPSV);
}

// --------------- fused resize + total/wmean/variance (one pass) ------------
__device__ __forceinline__ void resize_coords(int y, int x, int& y0, int& y1,
                                              int& x0, int& x1, float& wy, float& wx) {
    const float S = (float)PHW / (float)IMG;
    float sy = (y + 0.5f) * S - 0.5f;
    float sx = (x + 0.5f) * S - 0.5f;
    float fy = floorf(sy), fx = floorf(sx);
    wy = sy - fy;
    wx = sx - fx;
    y0 = max((int)fy, 0); y1 = min((int)fy + 1, PHW - 1);
    x0 = max((int)fx, 0); x1 = min((int)fx + 1, PHW - 1);
}

__device__ __forceinline__ float bilerp(const float* fb, int y0, int y1, int x0,
                                        int x1, float wy, float wx) {
    float a = fb[y0 * PHW + x0], b = fb[y0 * PHW + x1];
    float c = fb[y1 * PHW + x0], d = fb[y1 * PHW + x1];
    float top = a + (b - a) * wx;
    float bot = c + (d - c) * wx;
    return top + (bot - top) * wy;
}

__global__ __launch_bounds__(256) void fusedvar_kernel(const float* __restrict__ original) {
    int p = blockIdx.x * blockDim.x + threadIdx.x;
    int tid = threadIdx.x;
    float acc = 0.0f;
    if (p < IMG * IMG) {
        int y = p >> 9, x = p & 511;
        int y0, y1, x0, x1; float wy, wx;
        resize_coords(y, x, y0, y1, x0, x1, wy, wx);
        float r[NB];
        float o0[NB], o1[NB], o2[NB];
        float tot = 0.0f, wm0 = 0.0f, wm1 = 0.0f, wm2 = 0.0f;
#pragma unroll
        for (int b = 0; b < NB; b++) {
            r[b] = bilerp(g_final[b], y0, y1, x0, x1, wy, wx);
            tot += r[b];
            size_t base = ((size_t)b * 3) * (IMG * IMG) + p;
            o0[b] = original[base];
            o1[b] = original[base + IMG * IMG];
            o2[b] = original[base + 2 * IMG * IMG];
            wm0 = fmaf(o0[b], r[b], wm0);
            wm1 = fmaf(o1[b], r[b], wm1);
            wm2 = fmaf(o2[b], r[b], wm2);
        }
        float tinv = 1.0f / (tot + EPSV);
#pragma unroll
        for (int b = 0; b < NB; b++) {
            float d0 = o0[b] - wm0;
            float d1 = o1[b] - wm1;
            float d2 = o2[b] - wm2;
            acc = fmaf((d0 * d0 + d1 * d1 + d2 * d2), r[b], acc);
        }
        acc *= tinv;
    }
    // block reduce (256 threads)
    for (int o = 16; o > 0; o >>= 1) acc += __shfl_down_sync(0xFFFFFFFFu, acc, o);
    __shared__ float rs[8];
    int w = tid >> 5;
    if ((tid & 31) == 0) rs[w] = acc;
    __syncthreads();
    if (tid == 0) {
        float s = 0.0f;
#pragma unroll
        for (int i = 0; i < 8; i++) s += rs[i];
        g_varpart[blockIdx.x] = s;
    }
}

// ------------------------------ finalize -----------------------------------
__global__ void finalize_kernel(float* __restrict__ out) {
    __shared__ double sm[256];
    int tid = threadIdx.x;
    double a = 0.0;
    for (int i = tid; i < 1024; i += 256) a += (double)g_varpart[i];
    sm[tid] = a;
    __syncthreads();
    for (int s = 128; s > 0; s >>= 1) {
        if (tid < s) sm[tid] += sm[tid + s];
        __syncthreads();
    }
    if (tid == 0) out[0] = (float)sm[0];
    __syncthreads();
    double l = 0.0;
    const float* lp = &g_losspair[0][0];
    for (int i = tid; i < NB * 256; i += 256) l += (double)lp[i];
    sm[tid] = l;
    __syncthreads();
    for (int s = 128; s > 0; s >>= 1) {
        if (tid < s) sm[tid] += sm[tid + s];
        __syncthreads();
    }
    if (tid == 0) out[1] = (float)sm[0];
}

// ------------------------------ launcher -----------------------------------
extern "C" void kernel_launch(void* const* d_in, const int* in_sizes, int n_in,
                              void* d_out, int out_size) {
    const float* original = (const float*)d_in[0];
    const float* loc      = (const float*)d_in[1];
    const float* conf     = (const float*)d_in[2];
    const float* mask     = (const float*)d_in[3];
    const float* proto    = (const float*)d_in[4];
    const float* W1       = (const float*)d_in[5];
    const float* b1       = (const float*)d_in[6];
    const float* W2       = (const float*)d_in[7];
    const float* b2       = (const float*)d_in[8];
    float* out = (float*)d_out;

    topk_kernel<<<NB, 1024>>>(conf, loc, mask);
    tables_kernel<<<(NB * TK * MIDW + 255) / 256, 256>>>(W1, b1);
    mlp_kernel<<<dim3((TK + 15) / 16, (TK + 15) / 16, NB), 256>>>(W2, b2);
    nms_kernel<<<NB, 256>>>();
    loss_kernel<<<dim3(256, NB), 128>>>();
    gauss_kernel<<<dim3(TK, NB), 160>>>();
    attn_kernel<<<dim3((PHW * PHW + 255) / 256, NB), 256>>>(proto);
    fusedvar_kernel<<<(IMG * IMG) / 256, 256>>>(original);
    finalize_kernel<<<1, 256>>>(out);
}

// round 7
// speedup vs baseline: 2.0690x; 1.4833x over previous
#include <cuda_runtime.h>
#include <math.h>

#define NB 8
#define NP 19248
#define MDIM 32
#define TK 200
#define PHW 138
#define IMG 512
#define MIDW 64
#define GSAMP 16
#define GDIM 64
#define EPSV 1e-6f
#define CONF_TH 0.05f
#define NMS_TH 0.5f
#define MAXDET 100

// ------------------------------ scratch ------------------------------------
__device__ float g_conf_k[NB][TK];
__device__ int   g_validk[NB][TK];
__device__ float g_loc_k[NB][TK][4];
__device__ float g_mask_k[NB][TK][MDIM];
__device__ float g_Atab[NB][TK][MIDW];
__device__ float g_Btab[NB][TK][MIDW];
__device__ float g_iou[NB][TK][TK];
__device__ int   g_ioumaxI[NB][TK];
__device__ int   g_nkeep[NB];
__device__ int   g_perm[NB][TK];
__device__ float g_gy[NB][MAXDET][PHW];
__device__ float g_gx[NB][MAXDET][PHW];
__device__ float g_final[NB][PHW * PHW];
__device__ unsigned long long g_acc_var;
__device__ unsigned long long g_acc_loss;

#define SCALE_V 262144.0          /* 2^18 */
#define SCALE_L 1099511627776.0   /* 2^40 */

__device__ __forceinline__ unsigned enc_float(float v) {
    unsigned u = __float_as_uint(v);
    return (u & 0x80000000u) ? ~u : (u | 0x80000000u);
}

// ------------------- top-k + MLP factor tables (fused) ---------------------
__global__ __launch_bounds__(1024) void topk_kernel(const float* __restrict__ conf,
                                                    const float* __restrict__ loc,
                                                    const float* __restrict__ mask,
                                                    const float* __restrict__ W1,
                                                    const float* __restrict__ b1) {
    int b = blockIdx.x;
    int tid = threadIdx.x;
    const float* cp = conf + (size_t)b * NP * 2;

    __shared__ unsigned hist[256];
    __shared__ int s_scan[256];
    __shared__ unsigned s_prefix;
    __shared__ int s_remaining;
    __shared__ int s_cnt;
    __shared__ unsigned long long cand[1024];
    __shared__ unsigned long long s_sorted[TK];
    __shared__ int s_idx[TK];
    __shared__ float s_loc[TK * 4];

    if (b == 0 && tid == 0) { g_acc_var = 0ull; g_acc_loss = 0ull; }
    if (tid == 0) { s_prefix = 0u; s_remaining = TK; }
    __syncthreads();

    for (int pass = 0; pass < 3; pass++) {
        if (tid < 256) hist[tid] = 0u;
        __syncthreads();
        unsigned prefix = s_prefix;
        int shift_bin = 24 - 8 * pass;
        for (int i = tid; i < NP; i += 1024) {
            float c1 = cp[i * 2 + 1];
            float s = (c1 > CONF_TH) ? c1 : -1.0f;
            unsigned e = enc_float(s);
            unsigned hi = (pass == 0) ? 0u : (e >> (shift_bin + 8));
            if (hi == prefix) atomicAdd(&hist[(e >> shift_bin) & 0xFFu], 1u);
        }
        __syncthreads();
        // parallel suffix-sum over 256 bins (all threads pass through syncs)
        if (tid < 256) s_scan[tid] = (int)hist[tid];
        __syncthreads();
        for (int off = 1; off < 256; off <<= 1) {
            int v = 0, a = 0;
            if (tid < 256) { v = s_scan[tid]; a = (tid + off < 256) ? s_scan[tid + off] : 0; }
            __syncthreads();
            if (tid < 256) s_scan[tid] = v + a;
            __syncthreads();
        }
        int rem = s_remaining;
        if (tid < 256) {
            int sfx = s_scan[tid];
            int nxt = (tid < 255) ? s_scan[tid + 1] : 0;
            if (sfx >= rem && nxt < rem) {   // exactly one bin matches
                s_prefix = (s_prefix << 8) | (unsigned)tid;
                s_remaining = rem - nxt;
            }
        }
        __syncthreads();
    }

    if (tid == 0) s_cnt = 0;
    __syncthreads();
    unsigned thr24 = s_prefix;
    for (int i = tid; i < NP; i += 1024) {
        float c1 = cp[i * 2 + 1];
        float s = (c1 > CONF_TH) ? c1 : -1.0f;
        unsigned e = enc_float(s);
        if ((e >> 8) >= thr24) {
            int pos = atomicAdd(&s_cnt, 1);
            if (pos < 1024)
                cand[pos] = ((unsigned long long)e << 32) |
                            (unsigned long long)(0xFFFFFFFFu - (unsigned)i);
        }
    }
    __syncthreads();
    int cnt = min(s_cnt, 1024);

    // rank-select: rank = number of strictly greater keys (keys unique)
    if (tid < cnt) {
        unsigned long long key = cand[tid];
        int rank = 0;
        for (int i = 0; i < cnt; i++) rank += (cand[i] > key) ? 1 : 0;
        if (rank < TK) s_sorted[rank] = key;
    }
    __syncthreads();

    if (tid < TK) {
        unsigned long long key = s_sorted[tid];
        unsigned e = (unsigned)(key >> 32);
        int idx = (int)(0xFFFFFFFFu - (unsigned)(key & 0xFFFFFFFFull));
        unsigned u = (e & 0x80000000u) ? (e ^ 0x80000000u) : ~e;
        float v = __uint_as_float(u);
        int val = (v > CONF_TH) ? 1 : 0;
        g_validk[b][tid] = val;
        g_conf_k[b][tid] = val ? v : 0.0f;
        g_ioumaxI[b][tid] = 0;
        s_idx[tid] = idx;
    }
    __syncthreads();

    // parallel gather: loc and mask
    for (int t = tid; t < TK * 4; t += 1024) {
        int k = t >> 2, d = t & 3;
        float v = loc[((size_t)b * NP + s_idx[k]) * 4 + d];
        g_loc_k[b][k][d] = v;
        s_loc[t] = v;
    }
    for (int t = tid; t < TK * MDIM; t += 1024) {
        int k = t >> 5, d = t & 31;
        g_mask_k[b][k][d] = mask[((size_t)b * NP + s_idx[k]) * MDIM + d];
    }
    __syncthreads();

    // MLP factor tables: A = loc_j . W1[0:4], B = loc_i . W1[4:8] + b1
    for (int t = tid; t < TK * MIDW; t += 1024) {
        int k = t / MIDW, h = t % MIDW;
        float l0 = s_loc[k * 4 + 0], l1 = s_loc[k * 4 + 1];
        float l2 = s_loc[k * 4 + 2], l3 = s_loc[k * 4 + 3];
        float a = fmaf(l3, W1[3 * MIDW + h],
                  fmaf(l2, W1[2 * MIDW + h],
                  fmaf(l1, W1[1 * MIDW + h], l0 * W1[h])));
        float bb = fmaf(l3, W1[7 * MIDW + h],
                   fmaf(l2, W1[6 * MIDW + h],
                   fmaf(l1, W1[5 * MIDW + h], l0 * W1[4 * MIDW + h]))) + b1[h];
        g_Atab[b][k][h] = a;
        g_Btab[b][k][h] = bb;
    }
}

// -------------------------- 200x200 IoU MLP + column max -------------------
__global__ void mlp_kernel(const float* __restrict__ W2, const float* __restrict__ b2) {
    int b = blockIdx.z;
    int jb = blockIdx.x * 16, ib = blockIdx.y * 16;
    __shared__ float As[16][MIDW + 1];
    __shared__ float Bs[16][MIDW + 1];
    __shared__ float w2s[MIDW];
    __shared__ float s_b2;
    __shared__ int s_vi[16], s_vj[16];
    int tid = threadIdx.x;
    for (int t = tid; t < 16 * MIDW; t += 256) {
        int r = t / MIDW, h = t % MIDW;
        As[r][h] = (jb + r < TK) ? g_Atab[b][jb + r][h] : 0.0f;
        Bs[r][h] = (ib + r < TK) ? g_Btab[b][ib + r][h] : 0.0f;
    }
    if (tid < MIDW) w2s[tid] = W2[tid];
    if (tid == 0) s_b2 = b2[0];
    if (tid < 16) {
        s_vj[tid] = (jb + tid < TK) ? g_validk[b][jb + tid] : 0;
        s_vi[tid] = (ib + tid < TK) ? g_validk[b][ib + tid] : 0;
    }
    __syncthreads();
    int tj = tid & 15, ti = tid >> 4;
    int i = ib + ti, j = jb + tj;
    if (i < TK && j < TK) {
        float acc = s_b2;
#pragma unroll
        for (int h = 0; h < MIDW; h++) {
            float s = As[tj][h] + Bs[ti][h];
            acc = fmaf(fmaxf(s, 0.0f), w2s[h], acc);
        }
        float iou = __fdividef(1.0f, 1.0f + __expf(-acc));
        g_iou[b][i][j] = iou;
        if (i < j && s_vi[ti] && s_vj[tj])
            atomicMax(&g_ioumaxI[b][j], __float_as_int(iou));
    }
}

// ----------------- NMS (shfl scan) + gaussian tables (fused) ---------------
__global__ __launch_bounds__(256) void nms_kernel() {
    int b = blockIdx.x, tid = threadIdx.x;
    __shared__ int s_perm[TK];
    __shared__ int wsum[8];
    __shared__ float s_kloc[MAXDET * 4];
    __shared__ int s_nk;

    int keep = 0;
    if (tid < TK) {
        int valid = g_validk[b][tid];
        float m = __int_as_float(g_ioumaxI[b][tid]);
        keep = (valid && m <= NMS_TH) ? 1 : 0;
    }
    // two-level inclusive scan over 256 threads
    int lane = tid & 31, wid = tid >> 5;
    int v = keep;
#pragma unroll
    for (int o = 1; o < 32; o <<= 1) {
        int n = __shfl_up_sync(0xFFFFFFFFu, v, o);
        if (lane >= o) v += n;
    }
    if (lane == 31) wsum[wid] = v;
    __syncthreads();
    if (tid < 8) {
        int w = wsum[tid];
#pragma unroll
        for (int o = 1; o < 8; o <<= 1) {
            int n = __shfl_up_sync(0xFFu, w, o);
            if ((int)tid >= o) w += n;
        }
        wsum[tid] = w;
    }
    __syncthreads();
    int incl = v + (wid ? wsum[wid - 1] : 0);
    int total = wsum[7];
    int nk = min(total, MAXDET);
    int keep2 = keep && (incl <= MAXDET);
    int incl2 = min(incl, MAXDET);
    if (tid == 0) { g_nkeep[b] = nk; s_nk = nk; }
    if (tid < TK) {
        int pos = keep2 ? (incl2 - 1) : (nk + tid - incl2);
        s_perm[pos] = tid;
    }
    __syncthreads();
    if (tid < TK) g_perm[b][tid] = s_perm[tid];
    nk = s_nk;
    for (int t = tid; t < nk * 4; t += 256) {
        int k = t >> 2, d = t & 3;
        s_kloc[t] = g_loc_k[b][s_perm[k]][d];
    }
    __syncthreads();
    // gaussian row/col tables for the kept detections
    for (int k = 0; k < nk; k++) {
        if (tid < PHW) {
            float cx = s_kloc[k * 4 + 0], cy = s_kloc[k * 4 + 1];
            float bw = s_kloc[k * 4 + 2], bh = s_kloc[k * 4 + 3];
            float s = (tid + 0.5f) / (float)PHW;
            float ty = (s - cy) / (bh * 0.5f + EPSV);
            float tx = (s - cx) / (bw * 0.5f + EPSV);
            g_gy[b][k][tid] = __expf(-0.5f * ty * ty);
            g_gx[b][k][tid] = __expf(-0.5f * tx * tx);
        }
    }
}

// --------------------------- gaussian IoU loss -----------------------------
__global__ void loss_kernel() {
    int b = blockIdx.y;
    int pr = blockIdx.x;  // 0..255
    int p = pr >> 4, q = pr & 15;
    int tid = threadIdx.x;
    int g = min(GSAMP, g_nkeep[b]);
    if (p >= g || q >= g) return;
    __shared__ float gyp[GDIM], gxp[GDIM], gyq[GDIM], gxq[GDIM];
    __shared__ float ri[4], ru[4];
    int ip = g_perm[b][p], iq = g_perm[b][q];
    float cxp = g_loc_k[b][ip][0], cyp = g_loc_k[b][ip][1];
    float bwp = g_loc_k[b][ip][2], bhp = g_loc_k[b][ip][3];
    float cxq = g_loc_k[b][iq][0], cyq = g_loc_k[b][iq][1];
    float bwq = g_loc_k[b][iq][2], bhq = g_loc_k[b][iq][3];
    if (tid < GDIM) {
        float s = (tid + 0.5f) / (float)GDIM;
        float ty = (s - cyp) / (bhp * 0.5f + EPSV); gyp[tid] = __expf(-0.5f * ty * ty);
        float tx = (s - cxp) / (bwp * 0.5f + EPSV); gxp[tid] = __expf(-0.5f * tx * tx);
        float uy = (s - cyq) / (bhq * 0.5f + EPSV); gyq[tid] = __expf(-0.5f * uy * uy);
        float ux = (s - cxq) / (bwq * 0.5f + EPSV); gxq[tid] = __expf(-0.5f * ux * ux);
    }
    __syncthreads();
    float inter = 0.0f, uni = 0.0f;
    for (int pix = tid; pix < GDIM * GDIM; pix += blockDim.x) {
        int y = pix >> 6, x = pix & 63;
        float a = gyp[y] * gxp[x];
        float c = gyq[y] * gxq[x];
        inter += fminf(a, c);
        uni += fmaxf(a, c);
    }
    for (int o = 16; o > 0; o >>= 1) {
        inter += __shfl_down_sync(0xFFFFFFFFu, inter, o);
        uni   += __shfl_down_sync(0xFFFFFFFFu, uni, o);
    }
    int w = tid >> 5;
    if ((tid & 31) == 0) { ri[w] = inter; ru[w] = uni; }
    __syncthreads();
    if (tid == 0) {
        float I = ri[0] + ri[1] + ri[2] + ri[3];
        float U = ru[0] + ru[1] + ru[2] + ru[3];
        float giou = I / (U + EPSV);
        float pred = g_iou[b][ip][iq];
        float d = pred - giou;
        float result = d * d;
        atomicAdd(&g_acc_loss, (unsigned long long)((double)result * SCALE_L + 0.5));
    }
}

// -------------------- attention / final 138x138 map ------------------------
__global__ __launch_bounds__(256) void attn_kernel(const float* __restrict__ proto) {
    int b = blockIdx.y;
    int tid = threadIdx.x;
    int nk = g_nkeep[b];
    __shared__ int s_permk[MAXDET];
    __shared__ float s_mask[MAXDET * MDIM];
    __shared__ float s_conf[MAXDET];
    if (tid < nk) {
        int pk = g_perm[b][tid];
        s_permk[tid] = pk;
        s_conf[tid] = g_conf_k[b][pk];
    }
    __syncthreads();
    for (int t = tid; t < nk * MDIM; t += 256)
        s_mask[t] = g_mask_k[b][s_permk[t >> 5]][t & 31];
    __syncthreads();
    int p = blockIdx.x * 256 + tid;
    if (p >= PHW * PHW) return;
    int y = p / PHW, x = p % PHW;
    const float4* pp =
        reinterpret_cast<const float4*>(proto + (((size_t)b * PHW + y) * PHW + x) * MDIM);
    float4 pr[8];
#pragma unroll
    for (int i = 0; i < 8; i++) pr[i] = pp[i];
    float s1 = 0.0f, s2 = 0.0f;
    const float* gyb = &g_gy[b][0][0];
    const float* gxb = &g_gx[b][0][0];
    for (int k = 0; k < nk; k++) {
        const float4* mk = reinterpret_cast<const float4*>(&s_mask[k * MDIM]);
        float dot = 0.0f;
#pragma unroll
        for (int i = 0; i < 8; i++) {
            float4 m = mk[i];
            dot = fmaf(pr[i].x, m.x, dot);
            dot = fmaf(pr[i].y, m.y, dot);
            dot = fmaf(pr[i].z, m.z, dot);
            dot = fmaf(pr[i].w, m.w, dot);
        }
        float sg = __fdividef(1.0f, 1.0f + __expf(-dot));
        float mv = sg * __ldg(gyb + k * PHW + y) * __ldg(gxb + k * PHW + x) * s_conf[k];
        s1 += mv;
        s2 = fmaf(mv, mv, s2);
    }
    g_final[b][p] = 1.0f - s2 / (s1 + EPSV);
}

// --------- fused resize + total/wmean/variance (one pass) ------------------
__device__ __forceinline__ void resize_coords(int y, int x, int& y0, int& y1,
                                              int& x0, int& x1, float& wy, float& wx) {
    const float S = (float)PHW / (float)IMG;
    float sy = (y + 0.5f) * S - 0.5f;
    float sx = (x + 0.5f) * S - 0.5f;
    float fy = floorf(sy), fx = floorf(sx);
    wy = sy - fy;
    wx = sx - fx;
    y0 = max((int)fy, 0); y1 = min((int)fy + 1, PHW - 1);
    x0 = max((int)fx, 0); x1 = min((int)fx + 1, PHW - 1);
}

__device__ __forceinline__ float bilerp(const float* fb, int y0, int y1, int x0,
                                        int x1, float wy, float wx) {
    float a = fb[y0 * PHW + x0], b = fb[y0 * PHW + x1];
    float c = fb[y1 * PHW + x0], d = fb[y1 * PHW + x1];
    float top = a + (b - a) * wx;
    float bot = c + (d - c) * wx;
    return top + (bot - top) * wy;
}

__global__ __launch_bounds__(256) void fusedvar_kernel(const float* __restrict__ original) {
    int p = blockIdx.x * blockDim.x + threadIdx.x;
    int tid = threadIdx.x;
    float acc = 0.0f;
    if (p < IMG * IMG) {
        int y = p >> 9, x = p & 511;
        int y0, y1, x0, x1; float wy, wx;
        resize_coords(y, x, y0, y1, x0, x1, wy, wx);
        float r[NB];
        float o0[NB], o1[NB], o2[NB];
        float tot = 0.0f, wm0 = 0.0f, wm1 = 0.0f, wm2 = 0.0f;
#pragma unroll
        for (int b = 0; b < NB; b++) {
            r[b] = bilerp(g_final[b], y0, y1, x0, x1, wy, wx);
            tot += r[b];
            size_t base = ((size_t)b * 3) * (IMG * IMG) + p;
            o0[b] = original[base];
            o1[b] = original[base + IMG * IMG];
            o2[b] = original[base + 2 * IMG * IMG];
            wm0 = fmaf(o0[b], r[b], wm0);
            wm1 = fmaf(o1[b], r[b], wm1);
            wm2 = fmaf(o2[b], r[b], wm2);
        }
        float tinv = 1.0f / (tot + EPSV);
#pragma unroll
        for (int b = 0; b < NB; b++) {
            float d0 = o0[b] - wm0;
            float d1 = o1[b] - wm1;
            float d2 = o2[b] - wm2;
            acc = fmaf((d0 * d0 + d1 * d1 + d2 * d2), r[b], acc);
        }
        acc *= tinv;
    }
    // block reduce
    for (int o = 16; o > 0; o >>= 1) acc += __shfl_down_sync(0xFFFFFFFFu, acc, o);
    __shared__ float rs[8];
    int w = tid >> 5;
    if ((tid & 31) == 0) rs[w] = acc;
    __syncthreads();
    if (tid == 0) {
        float s = 0.0f;
#pragma unroll
        for (int i = 0; i < 8; i++) s += rs[i];
        atomicAdd(&g_acc_var, (unsigned long long)((double)s * SCALE_V + 0.5));
    }
}

// ------------------------------ finalize -----------------------------------
__global__ void finalize_kernel(float* __restrict__ out) {
    out[0] = (float)((double)g_acc_var / SCALE_V);
    out[1] = (float)((double)g_acc_loss / SCALE_L);
}

// ------------------------------ launcher -----------------------------------
extern "C" void kernel_launch(void* const* d_in, const int* in_sizes, int n_in,
                              void* d_out, int out_size) {
    const float* original = (const float*)d_in[0];
    const float* loc      = (const float*)d_in[1];
    const float* conf     = (const float*)d_in[2];
    const float* mask     = (const float*)d_in[3];
    const float* proto    = (const float*)d_in[4];
    const float* W1       = (const float*)d_in[5];
    const float* b1       = (const float*)d_in[6];
    const float* W2       = (const float*)d_in[7];
    const float* b2       = (const float*)d_in[8];
    float* out = (float*)d_out;

    topk_kernel<<<NB, 1024>>>(conf, loc, mask, W1, b1);
    mlp_kernel<<<dim3((TK + 15) / 16, (TK + 15) / 16, NB), 256>>>(W2, b2);
    nms_kernel<<<NB, 256>>>();
    loss_kernel<<<dim3(256, NB), 128>>>();
    attn_kernel<<<dim3((PHW * PHW + 255) / 256, NB), 256>>>(proto);
    fusedvar_kernel<<<(IMG * IMG) / 256, 256>>>(original);
    finalize_kernel<<<1, 1>>>(out);
}

// round 8
// speedup vs baseline: 2.1417x; 1.0351x over previous
#include <cuda_runtime.h>
#include <math.h>

#define NB 8
#define NP 19248
#define MDIM 32
#define TK 200
#define PHW 138
#define IMG 512
#define MIDW 64
#define GSAMP 16
#define GDIM 64
#define EPSV 1e-6f
#define CONF_TH 0.05f
#define NMS_TH 0.5f
#define MAXDET 100

// ------------------------------ scratch ------------------------------------
__device__ float g_conf_k[NB][TK];
__device__ int   g_validk[NB][TK];
__device__ float g_loc_k[NB][TK][4];
__device__ float g_mask_k[NB][TK][MDIM];
__device__ float g_Atab[NB][TK][MIDW];
__device__ float g_Btab[NB][TK][MIDW];
__device__ float g_iou[NB][TK][TK];
__device__ int   g_ioumaxI[NB][TK];
__device__ int   g_nkeep[NB];
__device__ int   g_perm[NB][TK];
__device__ float g_gy[NB][MAXDET][PHW];
__device__ float g_gx[NB][MAXDET][PHW];
__device__ float g_g64y[NB][GSAMP][GDIM];
__device__ float g_g64x[NB][GSAMP][GDIM];
__device__ float g_final[NB][PHW * PHW];
__device__ unsigned long long g_acc_var;
__device__ unsigned long long g_acc_loss;

#define SCALE_V 262144.0          /* 2^18 */
#define SCALE_L 1099511627776.0   /* 2^40 */

__device__ __forceinline__ unsigned enc_float(float v) {
    unsigned u = __float_as_uint(v);
    return (u & 0x80000000u) ? ~u : (u | 0x80000000u);
}

// ------------------- top-k + MLP factor tables (fused) ---------------------
__global__ __launch_bounds__(1024) void topk_kernel(const float* __restrict__ conf,
                                                    const float* __restrict__ loc,
                                                    const float* __restrict__ mask,
                                                    const float* __restrict__ W1,
                                                    const float* __restrict__ b1) {
    int b = blockIdx.x;
    int tid = threadIdx.x;
    const float* cp = conf + (size_t)b * NP * 2;

    __shared__ unsigned hist[256];
    __shared__ int wtot[8];
    __shared__ unsigned s_prefix;
    __shared__ int s_remaining;
    __shared__ int s_cnt;
    __shared__ unsigned long long cand[1024];
    __shared__ unsigned long long s_sorted[TK];
    __shared__ int s_idx[TK];
    __shared__ float s_loc[TK * 4];

    if (b == 0 && tid == 0) { g_acc_var = 0ull; g_acc_loss = 0ull; }
    if (tid == 0) { s_prefix = 0u; s_remaining = TK; }
    __syncthreads();

    int lane = tid & 31;
    for (int pass = 0; pass < 3; pass++) {
        if (tid < 256) hist[tid] = 0u;
        __syncthreads();
        unsigned prefix = s_prefix;
        int shift_bin = 24 - 8 * pass;
        for (int i = tid; i < NP; i += 1024) {
            float c1 = cp[i * 2 + 1];
            float s = (c1 > CONF_TH) ? c1 : -1.0f;
            unsigned e = enc_float(s);
            unsigned hi = (pass == 0) ? 0u : (e >> (shift_bin + 8));
            if (hi == prefix) atomicAdd(&hist[(e >> shift_bin) & 0xFFu], 1u);
        }
        __syncthreads();
        int rem = s_remaining;   // read before any thread may write it
        // warp-level suffix scan over 256 bins (threads 0..255 = 8 warps)
        int h = 0, sfxv = 0;
        if (tid < 256) {
            h = (int)hist[tid];
            sfxv = h;
#pragma unroll
            for (int off = 1; off < 32; off <<= 1) {
                int n = __shfl_down_sync(0xFFFFFFFFu, sfxv, off);
                if (lane + off < 32) sfxv += n;
            }
            if (lane == 0) wtot[tid >> 5] = sfxv;
        }
        __syncthreads();
        if (tid < 256) {
            int add = 0;
            for (int wg = (tid >> 5) + 1; wg < 8; wg++) add += wtot[wg];
            int sfx = sfxv + add;
            int nxt = sfx - h;
            if (sfx >= rem && nxt < rem) {   // exactly one bin matches
                s_prefix = (s_prefix << 8) | (unsigned)tid;
                s_remaining = rem - nxt;
            }
        }
        __syncthreads();
    }

    if (tid == 0) s_cnt = 0;
    __syncthreads();
    unsigned thr24 = s_prefix;
    for (int i = tid; i < NP; i += 1024) {
        float c1 = cp[i * 2 + 1];
        float s = (c1 > CONF_TH) ? c1 : -1.0f;
        unsigned e = enc_float(s);
        if ((e >> 8) >= thr24) {
            int pos = atomicAdd(&s_cnt, 1);
            if (pos < 1024)
                cand[pos] = ((unsigned long long)e << 32) |
                            (unsigned long long)(0xFFFFFFFFu - (unsigned)i);
        }
    }
    __syncthreads();
    int cnt = min(s_cnt, 1024);

    // rank-select: rank = number of strictly greater keys (keys unique)
    if (tid < cnt) {
        unsigned long long key = cand[tid];
        int rank = 0;
        for (int i = 0; i < cnt; i++) rank += (cand[i] > key) ? 1 : 0;
        if (rank < TK) s_sorted[rank] = key;
    }
    __syncthreads();

    if (tid < TK) {
        unsigned long long key = s_sorted[tid];
        unsigned e = (unsigned)(key >> 32);
        int idx = (int)(0xFFFFFFFFu - (unsigned)(key & 0xFFFFFFFFull));
        unsigned u = (e & 0x80000000u) ? (e ^ 0x80000000u) : ~e;
        float v = __uint_as_float(u);
        int val = (v > CONF_TH) ? 1 : 0;
        g_validk[b][tid] = val;
        g_conf_k[b][tid] = val ? v : 0.0f;
        g_ioumaxI[b][tid] = 0;
        s_idx[tid] = idx;
    }
    __syncthreads();

    // parallel gather: loc and mask
    for (int t = tid; t < TK * 4; t += 1024) {
        int k = t >> 2, d = t & 3;
        float v = loc[((size_t)b * NP + s_idx[k]) * 4 + d];
        g_loc_k[b][k][d] = v;
        s_loc[t] = v;
    }
    for (int t = tid; t < TK * MDIM; t += 1024) {
        int k = t >> 5, d = t & 31;
        g_mask_k[b][k][d] = mask[((size_t)b * NP + s_idx[k]) * MDIM + d];
    }
    __syncthreads();

    // MLP factor tables: A = loc_j . W1[0:4], B = loc_i . W1[4:8] + b1
    for (int t = tid; t < TK * MIDW; t += 1024) {
        int k = t / MIDW, h = t % MIDW;
        float l0 = s_loc[k * 4 + 0], l1 = s_loc[k * 4 + 1];
        float l2 = s_loc[k * 4 + 2], l3 = s_loc[k * 4 + 3];
        float a = fmaf(l3, W1[3 * MIDW + h],
                  fmaf(l2, W1[2 * MIDW + h],
                  fmaf(l1, W1[1 * MIDW + h], l0 * W1[h])));
        float bb = fmaf(l3, W1[7 * MIDW + h],
                   fmaf(l2, W1[6 * MIDW + h],
                   fmaf(l1, W1[5 * MIDW + h], l0 * W1[4 * MIDW + h]))) + b1[h];
        g_Atab[b][k][h] = a;
        g_Btab[b][k][h] = bb;
    }
}

// -------------------------- 200x200 IoU MLP + column max -------------------
__global__ void mlp_kernel(const float* __restrict__ W2, const float* __restrict__ b2) {
    int b = blockIdx.z;
    int jb = blockIdx.x * 16, ib = blockIdx.y * 16;
    __shared__ float As[16][MIDW + 1];
    __shared__ float Bs[16][MIDW + 1];
    __shared__ float w2s[MIDW];
    __shared__ float s_b2;
    __shared__ int s_vi[16], s_vj[16];
    int tid = threadIdx.x;
    for (int t = tid; t < 16 * MIDW; t += 256) {
        int r = t / MIDW, h = t % MIDW;
        As[r][h] = (jb + r < TK) ? g_Atab[b][jb + r][h] : 0.0f;
        Bs[r][h] = (ib + r < TK) ? g_Btab[b][ib + r][h] : 0.0f;
    }
    if (tid < MIDW) w2s[tid] = W2[tid];
    if (tid == 0) s_b2 = b2[0];
    if (tid < 16) {
        s_vj[tid] = (jb + tid < TK) ? g_validk[b][jb + tid] : 0;
        s_vi[tid] = (ib + tid < TK) ? g_validk[b][ib + tid] : 0;
    }
    __syncthreads();
    int tj = tid & 15, ti = tid >> 4;
    int i = ib + ti, j = jb + tj;
    if (i < TK && j < TK) {
        float acc = s_b2;
#pragma unroll
        for (int h = 0; h < MIDW; h++) {
            float s = As[tj][h] + Bs[ti][h];
            acc = fmaf(fmaxf(s, 0.0f), w2s[h], acc);
        }
        float iou = __fdividef(1.0f, 1.0f + __expf(-acc));
        g_iou[b][i][j] = iou;
        if (i < j && s_vi[ti] && s_vj[tj])
            atomicMax(&g_ioumaxI[b][j], __float_as_int(iou));
    }
}

// ------- NMS (shfl scan) + gaussian tables (PHW for attn, 64 for loss) -----
__global__ __launch_bounds__(256) void nms_kernel() {
    int b = blockIdx.x, tid = threadIdx.x;
    __shared__ int s_perm[TK];
    __shared__ int wsum[8];
    __shared__ float s_kloc[MAXDET * 4];
    __shared__ int s_nk;

    int keep = 0;
    if (tid < TK) {
        int valid = g_validk[b][tid];
        float m = __int_as_float(g_ioumaxI[b][tid]);
        keep = (valid && m <= NMS_TH) ? 1 : 0;
    }
    // two-level inclusive scan over 256 threads
    int lane = tid & 31, wid = tid >> 5;
    int v = keep;
#pragma unroll
    for (int o = 1; o < 32; o <<= 1) {
        int n = __shfl_up_sync(0xFFFFFFFFu, v, o);
        if (lane >= o) v += n;
    }
    if (lane == 31) wsum[wid] = v;
    __syncthreads();
    if (tid < 8) {
        int w = wsum[tid];
#pragma unroll
        for (int o = 1; o < 8; o <<= 1) {
            int n = __shfl_up_sync(0xFFu, w, o);
            if ((int)tid >= o) w += n;
        }
        wsum[tid] = w;
    }
    __syncthreads();
    int incl = v + (wid ? wsum[wid - 1] : 0);
    int total = wsum[7];
    int nk = min(total, MAXDET);
    int keep2 = keep && (incl <= MAXDET);
    int incl2 = min(incl, MAXDET);
    if (tid == 0) { g_nkeep[b] = nk; s_nk = nk; }
    if (tid < TK) {
        int pos = keep2 ? (incl2 - 1) : (nk + tid - incl2);
        s_perm[pos] = tid;
    }
    __syncthreads();
    if (tid < TK) g_perm[b][tid] = s_perm[tid];
    nk = s_nk;
    for (int t = tid; t < nk * 4; t += 256) {
        int k = t >> 2, d = t & 3;
        s_kloc[t] = g_loc_k[b][s_perm[k]][d];
    }
    __syncthreads();
    // gaussian row/col tables (PHW resolution) for attention
    for (int k = 0; k < nk; k++) {
        if (tid < PHW) {
            float cx = s_kloc[k * 4 + 0], cy = s_kloc[k * 4 + 1];
            float bw = s_kloc[k * 4 + 2], bh = s_kloc[k * 4 + 3];
            float s = (tid + 0.5f) / (float)PHW;
            float ty = (s - cy) / (bh * 0.5f + EPSV);
            float tx = (s - cx) / (bw * 0.5f + EPSV);
            g_gy[b][k][tid] = __expf(-0.5f * ty * ty);
            g_gx[b][k][tid] = __expf(-0.5f * tx * tx);
        }
    }
    // gaussian tables (GDIM=64 resolution) for the IoU loss samples
    int g = min(nk, GSAMP);
    for (int t = tid; t < g * GDIM; t += 256) {
        int k = t / GDIM, i = t % GDIM;
        float cx = s_kloc[k * 4 + 0], cy = s_kloc[k * 4 + 1];
        float bw = s_kloc[k * 4 + 2], bh = s_kloc[k * 4 + 3];
        float s = (i + 0.5f) / (float)GDIM;
        float ty = (s - cy) / (bh * 0.5f + EPSV);
        float tx = (s - cx) / (bw * 0.5f + EPSV);
        g_g64y[b][k][i] = __expf(-0.5f * ty * ty);
        g_g64x[b][k][i] = __expf(-0.5f * tx * tx);
    }
}

// --------------------------- gaussian IoU loss -----------------------------
// grid (GSAMP, NB); block 256 = 8 warps; warp handles q = warp, warp+8
__global__ __launch_bounds__(256) void loss_kernel() {
    int b = blockIdx.y, p = blockIdx.x;
    int g = min(GSAMP, g_nkeep[b]);
    if (p >= g) return;
    __shared__ float sy[GSAMP][GDIM];
    __shared__ float sx[GSAMP][GDIM];
    int tid = threadIdx.x;
    for (int t = tid; t < GSAMP * GDIM; t += 256) {
        int k = t / GDIM, i = t % GDIM;
        sy[k][i] = g_g64y[b][k][i];
        sx[k][i] = g_g64x[b][k][i];
    }
    __syncthreads();
    int warp = tid >> 5, lane = tid & 31;
    const float* gyp = sy[p];
    const float* gxp = sx[p];
    int ip = g_perm[b][p];
    for (int q = warp; q < g; q += 8) {
        const float* gyq = sy[q];
        const float* gxq = sx[q];
        float inter = 0.0f, uni = 0.0f;
        for (int px = lane; px < GDIM * GDIM; px += 32) {
            int y = px >> 6, x = px & 63;
            float a = gyp[y] * gxp[x];
            float c = gyq[y] * gxq[x];
            inter += fminf(a, c);
            uni += fmaxf(a, c);
        }
#pragma unroll
        for (int o = 16; o > 0; o >>= 1) {
            inter += __shfl_down_sync(0xFFFFFFFFu, inter, o);
            uni   += __shfl_down_sync(0xFFFFFFFFu, uni, o);
        }
        if (lane == 0) {
            float giou = inter / (uni + EPSV);
            float pred = g_iou[b][ip][g_perm[b][q]];
            float d = pred - giou;
            atomicAdd(&g_acc_loss, (unsigned long long)((double)(d * d) * SCALE_L + 0.5));
        }
    }
}

// -------------------- attention / final 138x138 map ------------------------
__global__ __launch_bounds__(256) void attn_kernel(const float* __restrict__ proto) {
    int b = blockIdx.y;
    int tid = threadIdx.x;
    int nk = g_nkeep[b];
    __shared__ int s_permk[MAXDET];
    __shared__ float s_mask[MAXDET * MDIM];
    __shared__ float s_conf[MAXDET];
    if (tid < nk) {
        int pk = g_perm[b][tid];
        s_permk[tid] = pk;
        s_conf[tid] = g_conf_k[b][pk];
    }
    __syncthreads();
    for (int t = tid; t < nk * MDIM; t += 256)
        s_mask[t] = g_mask_k[b][s_permk[t >> 5]][t & 31];
    __syncthreads();
    int p = blockIdx.x * 256 + tid;
    if (p >= PHW * PHW) return;
    int y = p / PHW, x = p % PHW;
    const float4* pp =
        reinterpret_cast<const float4*>(proto + (((size_t)b * PHW + y) * PHW + x) * MDIM);
    float4 pr[8];
#pragma unroll
    for (int i = 0; i < 8; i++) pr[i] = pp[i];
    float s1 = 0.0f, s2 = 0.0f;
    const float* gyb = &g_gy[b][0][0];
    const float* gxb = &g_gx[b][0][0];
    for (int k = 0; k < nk; k++) {
        const float4* mk = reinterpret_cast<const float4*>(&s_mask[k * MDIM]);
        float dot = 0.0f;
#pragma unroll
        for (int i = 0; i < 8; i++) {
            float4 m = mk[i];
            dot = fmaf(pr[i].x, m.x, dot);
            dot = fmaf(pr[i].y, m.y, dot);
            dot = fmaf(pr[i].z, m.z, dot);
            dot = fmaf(pr[i].w, m.w, dot);
        }
        float sg = __fdividef(1.0f, 1.0f + __expf(-dot));
        float mv = sg * __ldg(gyb + k * PHW + y) * __ldg(gxb + k * PHW + x) * s_conf[k];
        s1 += mv;
        s2 = fmaf(mv, mv, s2);
    }
    g_final[b][p] = 1.0f - s2 / (s1 + EPSV);
}

// --------- fused resize + total/wmean/variance (one pass) ------------------
__device__ __forceinline__ void resize_coords(int y, int x, int& y0, int& y1,
                                              int& x0, int& x1, float& wy, float& wx) {
    const float S = (float)PHW / (float)IMG;
    float sy = (y + 0.5f) * S - 0.5f;
    float sx = (x + 0.5f) * S - 0.5f;
    float fy = floorf(sy), fx = floorf(sx);
    wy = sy - fy;
    wx = sx - fx;
    y0 = max((int)fy, 0); y1 = min((int)fy + 1, PHW - 1);
    x0 = max((int)fx, 0); x1 = min((int)fx + 1, PHW - 1);
}

__device__ __forceinline__ float bilerp(const float* fb, int y0, int y1, int x0,
                                        int x1, float wy, float wx) {
    float a = fb[y0 * PHW + x0], b = fb[y0 * PHW + x1];
    float c = fb[y1 * PHW + x0], d = fb[y1 * PHW + x1];
    float top = a + (b - a) * wx;
    float bot = c + (d - c) * wx;
    return top + (bot - top) * wy;
}

__global__ __launch_bounds__(256) void fusedvar_kernel(const float* __restrict__ original) {
    int p = blockIdx.x * blockDim.x + threadIdx.x;
    int tid = threadIdx.x;
    float acc = 0.0f;
    if (p < IMG * IMG) {
        int y = p >> 9, x = p & 511;
        int y0, y1, x0, x1; float wy, wx;
        resize_coords(y, x, y0, y1, x0, x1, wy, wx);
        float r[NB];
        float o0[NB], o1[NB], o2[NB];
        float tot = 0.0f, wm0 = 0.0f, wm1 = 0.0f, wm2 = 0.0f;
#pragma unroll
        for (int b = 0; b < NB; b++) {
            r[b] = bilerp(g_final[b], y0, y1, x0, x1, wy, wx);
            tot += r[b];
            size_t base = ((size_t)b * 3) * (IMG * IMG) + p;
            o0[b] = original[base];
            o1[b] = original[base + IMG * IMG];
            o2[b] = original[base + 2 * IMG * IMG];
            wm0 = fmaf(o0[b], r[b], wm0);
            wm1 = fmaf(o1[b], r[b], wm1);
            wm2 = fmaf(o2[b], r[b], wm2);
        }
        float tinv = 1.0f / (tot + EPSV);
#pragma unroll
        for (int b = 0; b < NB; b++) {
            float d0 = o0[b] - wm0;
            float d1 = o1[b] - wm1;
            float d2 = o2[b] - wm2;
            acc = fmaf((d0 * d0 + d1 * d1 + d2 * d2), r[b], acc);
        }
        acc *= tinv;
    }
    // block reduce
    for (int o = 16; o > 0; o >>= 1) acc += __shfl_down_sync(0xFFFFFFFFu, acc, o);
    __shared__ float rs[8];
    int w = tid >> 5;
    if ((tid & 31) == 0) rs[w] = acc;
    __syncthreads();
    if (tid == 0) {
        float s = 0.0f;
#pragma unroll
        for (int i = 0; i < 8; i++) s += rs[i];
        atomicAdd(&g_acc_var, (unsigned long long)((double)s * SCALE_V + 0.5));
    }
}

// ------------------------------ finalize -----------------------------------
__global__ void finalize_kernel(float* __restrict__ out) {
    out[0] = (float)((double)g_acc_var / SCALE_V);
    out[1] = (float)((double)g_acc_loss / SCALE_L);
}

// ------------------------------ launcher -----------------------------------
extern "C" void kernel_launch(void* const* d_in, const int* in_sizes, int n_in,
                              void* d_out, int out_size) {
    const float* original = (const float*)d_in[0];
    const float* loc      = (const float*)d_in[1];
    const float* conf     = (const float*)d_in[2];
    const float* mask     = (const float*)d_in[3];
    const float* proto    = (const float*)d_in[4];
    const float* W1       = (const float*)d_in[5];
    const float* b1       = (const float*)d_in[6];
    const float* W2       = (const float*)d_in[7];
    const float* b2       = (const float*)d_in[8];
    float* out = (float*)d_out;

    topk_kernel<<<NB, 1024>>>(conf, loc, mask, W1, b1);
    mlp_kernel<<<dim3((TK + 15) / 16, (TK + 15) / 16, NB), 256>>>(W2, b2);
    nms_kernel<<<NB, 256>>>();
    loss_kernel<<<dim3(GSAMP, NB), 256>>>();
    attn_kernel<<<dim3((PHW * PHW + 255) / 256, NB), 256>>>(proto);
    fusedvar_kernel<<<(IMG * IMG) / 256, 256>>>(original);
    finalize_kernel<<<1, 1>>>(out);
}

// round 9
// speedup vs baseline: 2.4584x; 1.1479x over previous
#include <cuda_runtime.h>
#include <math.h>

#define NB 8
#define NP 19248
#define MDIM 32
#define TK 200
#define PHW 138
#define IMG 512
#define MIDW 64
#define GSAMP 16
#define GDIM 64
#define EPSV 1e-6f
#define CONF_TH 0.05f
#define NMS_TH 0.5f
#define MAXDET 100

#define NATT 75   /* ceil(PHW*PHW/256) */
#define NVALS 19  /* ceil(NP/1024) */

// ------------------------------ scratch ------------------------------------
__device__ float g_conf_k[NB][TK];
__device__ int   g_validk[NB][TK];
__device__ float g_loc_k[NB][TK][4];
__device__ float g_mask_k[NB][TK][MDIM];
__device__ float g_Atab[NB][TK][MIDW];
__device__ float g_Btab[NB][TK][MIDW];
__device__ float g_iou[NB][TK][TK];
__device__ int   g_ioumaxI[NB][TK];
__device__ int   g_nkeep[NB];
__device__ int   g_perm[NB][TK];
__device__ float g_gy[NB][MAXDET][PHW];
__device__ float g_gx[NB][MAXDET][PHW];
__device__ float g_g64y[NB][GSAMP][GDIM];
__device__ float g_g64x[NB][GSAMP][GDIM];
__device__ float g_final[NB][PHW * PHW];
__device__ unsigned long long g_acc_var;
__device__ unsigned long long g_acc_loss;

#define SCALE_V 262144.0          /* 2^18 */
#define SCALE_L 1099511627776.0   /* 2^40 */

__device__ __forceinline__ unsigned enc_float(float v) {
    unsigned u = __float_as_uint(v);
    return (u & 0x80000000u) ? ~u : (u | 0x80000000u);
}

// ------------------- top-k + MLP factor tables (fused) ---------------------
__global__ __launch_bounds__(1024) void topk_kernel(const float* __restrict__ conf,
                                                    const float* __restrict__ loc,
                                                    const float* __restrict__ mask,
                                                    const float* __restrict__ W1,
                                                    const float* __restrict__ b1) {
    int b = blockIdx.x;
    int tid = threadIdx.x;
    const float* cp = conf + (size_t)b * NP * 2;

    __shared__ unsigned hist[256];
    __shared__ int wtot[8];
    __shared__ unsigned s_prefix;
    __shared__ int s_remaining;
    __shared__ int s_cnt;
    __shared__ unsigned long long cand[1024];
    __shared__ unsigned long long s_sorted[TK];
    __shared__ int s_idx[TK];
    __shared__ float s_loc[TK * 4];

    if (b == 0 && tid == 0) { g_acc_var = 0ull; g_acc_loss = 0ull; }
    if (tid == 0) { s_prefix = 0u; s_remaining = TK; }

    // single global sweep: encode all values into registers (0 = OOB sentinel;
    // no real encoding is 0: positives map to >=0x80000000, -1.0 to 0x407FFFFF)
    unsigned enc[NVALS];
#pragma unroll
    for (int p = 0; p < NVALS; p++) {
        int i = tid + p * 1024;
        unsigned e = 0u;
        if (i < NP) {
            float c1 = cp[i * 2 + 1];
            float s = (c1 > CONF_TH) ? c1 : -1.0f;
            e = enc_float(s);
        }
        enc[p] = e;
    }
    __syncthreads();

    int lane = tid & 31;
    for (int pass = 0; pass < 3; pass++) {
        if (tid < 256) hist[tid] = 0u;
        __syncthreads();
        unsigned prefix = s_prefix;
        int shift_bin = 24 - 8 * pass;
#pragma unroll
        for (int p = 0; p < NVALS; p++) {
            unsigned e = enc[p];
            if (e != 0u) {
                unsigned hi = (pass == 0) ? 0u : (e >> (shift_bin + 8));
                if (hi == prefix) atomicAdd(&hist[(e >> shift_bin) & 0xFFu], 1u);
            }
        }
        __syncthreads();
        int rem = s_remaining;   // read before any thread may write it
        // warp-level suffix scan over 256 bins (threads 0..255 = 8 warps)
        int h = 0, sfxv = 0;
        if (tid < 256) {
            h = (int)hist[tid];
            sfxv = h;
#pragma unroll
            for (int off = 1; off < 32; off <<= 1) {
                int n = __shfl_down_sync(0xFFFFFFFFu, sfxv, off);
                if (lane + off < 32) sfxv += n;
            }
            if (lane == 0) wtot[tid >> 5] = sfxv;
        }
        __syncthreads();
        if (tid < 256) {
            int add = 0;
            for (int wg = (tid >> 5) + 1; wg < 8; wg++) add += wtot[wg];
            int sfx = sfxv + add;
            int nxt = sfx - h;
            if (sfx >= rem && nxt < rem) {   // exactly one bin matches
                s_prefix = (s_prefix << 8) | (unsigned)tid;
                s_remaining = rem - nxt;
            }
        }
        __syncthreads();
    }

    if (tid == 0) s_cnt = 0;
    __syncthreads();
    unsigned thr24 = s_prefix;
#pragma unroll
    for (int p = 0; p < NVALS; p++) {
        unsigned e = enc[p];
        if (e != 0u && (e >> 8) >= thr24) {
            int i = tid + p * 1024;
            int pos = atomicAdd(&s_cnt, 1);
            if (pos < 1024)
                cand[pos] = ((unsigned long long)e << 32) |
                            (unsigned long long)(0xFFFFFFFFu - (unsigned)i);
        }
    }
    __syncthreads();
    int cnt = min(s_cnt, 1024);

    // rank-select: rank = number of strictly greater keys (keys unique)
    if (tid < cnt) {
        unsigned long long key = cand[tid];
        int rank = 0;
        for (int i = 0; i < cnt; i++) rank += (cand[i] > key) ? 1 : 0;
        if (rank < TK) s_sorted[rank] = key;
    }
    __syncthreads();

    if (tid < TK) {
        unsigned long long key = s_sorted[tid];
        unsigned e = (unsigned)(key >> 32);
        int idx = (int)(0xFFFFFFFFu - (unsigned)(key & 0xFFFFFFFFull));
        unsigned u = (e & 0x80000000u) ? (e ^ 0x80000000u) : ~e;
        float v = __uint_as_float(u);
        int val = (v > CONF_TH) ? 1 : 0;
        g_validk[b][tid] = val;
        g_conf_k[b][tid] = val ? v : 0.0f;
        g_ioumaxI[b][tid] = 0;
        s_idx[tid] = idx;
    }
    __syncthreads();

    // parallel gather: loc and mask
    for (int t = tid; t < TK * 4; t += 1024) {
        int k = t >> 2, d = t & 3;
        float v = loc[((size_t)b * NP + s_idx[k]) * 4 + d];
        g_loc_k[b][k][d] = v;
        s_loc[t] = v;
    }
    for (int t = tid; t < TK * MDIM; t += 1024) {
        int k = t >> 5, d = t & 31;
        g_mask_k[b][k][d] = mask[((size_t)b * NP + s_idx[k]) * MDIM + d];
    }
    __syncthreads();

    // MLP factor tables: A = loc_j . W1[0:4], B = loc_i . W1[4:8] + b1
    for (int t = tid; t < TK * MIDW; t += 1024) {
        int k = t / MIDW, h = t % MIDW;
        float l0 = s_loc[k * 4 + 0], l1 = s_loc[k * 4 + 1];
        float l2 = s_loc[k * 4 + 2], l3 = s_loc[k * 4 + 3];
        float a = fmaf(l3, W1[3 * MIDW + h],
                  fmaf(l2, W1[2 * MIDW + h],
                  fmaf(l1, W1[1 * MIDW + h], l0 * W1[h])));
        float bb = fmaf(l3, W1[7 * MIDW + h],
                   fmaf(l2, W1[6 * MIDW + h],
                   fmaf(l1, W1[5 * MIDW + h], l0 * W1[4 * MIDW + h]))) + b1[h];
        g_Atab[b][k][h] = a;
        g_Btab[b][k][h] = bb;
    }
}

// -------------------------- 200x200 IoU MLP + column max -------------------
__global__ void mlp_kernel(const float* __restrict__ W2, const float* __restrict__ b2) {
    int b = blockIdx.z;
    int jb = blockIdx.x * 16, ib = blockIdx.y * 16;
    __shared__ float As[16][MIDW + 1];
    __shared__ float Bs[16][MIDW + 1];
    __shared__ float w2s[MIDW];
    __shared__ float s_b2;
    __shared__ int s_vi[16], s_vj[16];
    int tid = threadIdx.x;
    for (int t = tid; t < 16 * MIDW; t += 256) {
        int r = t / MIDW, h = t % MIDW;
        As[r][h] = (jb + r < TK) ? g_Atab[b][jb + r][h] : 0.0f;
        Bs[r][h] = (ib + r < TK) ? g_Btab[b][ib + r][h] : 0.0f;
    }
    if (tid < MIDW) w2s[tid] = W2[tid];
    if (tid == 0) s_b2 = b2[0];
    if (tid < 16) {
        s_vj[tid] = (jb + tid < TK) ? g_validk[b][jb + tid] : 0;
        s_vi[tid] = (ib + tid < TK) ? g_validk[b][ib + tid] : 0;
    }
    __syncthreads();
    int tj = tid & 15, ti = tid >> 4;
    int i = ib + ti, j = jb + tj;
    if (i < TK && j < TK) {
        float acc = s_b2;
#pragma unroll
        for (int h = 0; h < MIDW; h++) {
            float s = As[tj][h] + Bs[ti][h];
            acc = fmaf(fmaxf(s, 0.0f), w2s[h], acc);
        }
        float iou = __fdividef(1.0f, 1.0f + __expf(-acc));
        g_iou[b][i][j] = iou;
        if (i < j && s_vi[ti] && s_vj[tj])
            atomicMax(&g_ioumaxI[b][j], __float_as_int(iou));
    }
}

// ------- NMS (shfl scan) + gaussian tables (PHW for attn, 64 for loss) -----
__global__ __launch_bounds__(256) void nms_kernel() {
    int b = blockIdx.x, tid = threadIdx.x;
    __shared__ int s_perm[TK];
    __shared__ int wsum[8];
    __shared__ float s_kloc[MAXDET * 4];
    __shared__ int s_nk;

    int keep = 0;
    if (tid < TK) {
        int valid = g_validk[b][tid];
        float m = __int_as_float(g_ioumaxI[b][tid]);
        keep = (valid && m <= NMS_TH) ? 1 : 0;
    }
    // two-level inclusive scan over 256 threads
    int lane = tid & 31, wid = tid >> 5;
    int v = keep;
#pragma unroll
    for (int o = 1; o < 32; o <<= 1) {
        int n = __shfl_up_sync(0xFFFFFFFFu, v, o);
        if (lane >= o) v += n;
    }
    if (lane == 31) wsum[wid] = v;
    __syncthreads();
    if (tid < 8) {
        int w = wsum[tid];
#pragma unroll
        for (int o = 1; o < 8; o <<= 1) {
            int n = __shfl_up_sync(0xFFu, w, o);
            if ((int)tid >= o) w += n;
        }
        wsum[tid] = w;
    }
    __syncthreads();
    int incl = v + (wid ? wsum[wid - 1] : 0);
    int total = wsum[7];
    int nk = min(total, MAXDET);
    int keep2 = keep && (incl <= MAXDET);
    int incl2 = min(incl, MAXDET);
    if (tid == 0) { g_nkeep[b] = nk; s_nk = nk; }
    if (tid < TK) {
        int pos = keep2 ? (incl2 - 1) : (nk + tid - incl2);
        s_perm[pos] = tid;
    }
    __syncthreads();
    if (tid < TK) g_perm[b][tid] = s_perm[tid];
    nk = s_nk;
    for (int t = tid; t < nk * 4; t += 256) {
        int k = t >> 2, d = t & 3;
        s_kloc[t] = g_loc_k[b][s_perm[k]][d];
    }
    __syncthreads();
    // gaussian row/col tables (PHW resolution) for attention
    for (int k = 0; k < nk; k++) {
        if (tid < PHW) {
            float cx = s_kloc[k * 4 + 0], cy = s_kloc[k * 4 + 1];
            float bw = s_kloc[k * 4 + 2], bh = s_kloc[k * 4 + 3];
            float s = (tid + 0.5f) / (float)PHW;
            float ty = (s - cy) / (bh * 0.5f + EPSV);
            float tx = (s - cx) / (bw * 0.5f + EPSV);
            g_gy[b][k][tid] = __expf(-0.5f * ty * ty);
            g_gx[b][k][tid] = __expf(-0.5f * tx * tx);
        }
    }
    // gaussian tables (GDIM=64 resolution) for the IoU loss samples
    int g = min(nk, GSAMP);
    for (int t = tid; t < g * GDIM; t += 256) {
        int k = t / GDIM, i = t % GDIM;
        float cx = s_kloc[k * 4 + 0], cy = s_kloc[k * 4 + 1];
        float bw = s_kloc[k * 4 + 2], bh = s_kloc[k * 4 + 3];
        float s = (i + 0.5f) / (float)GDIM;
        float ty = (s - cy) / (bh * 0.5f + EPSV);
        float tx = (s - cx) / (bw * 0.5f + EPSV);
        g_g64y[b][k][i] = __expf(-0.5f * ty * ty);
        g_g64x[b][k][i] = __expf(-0.5f * tx * tx);
    }
}

// ---------- attention / final map + gaussian IoU loss (one launch) ---------
// grid (NATT + GSAMP, NB): blocks [0,NATT) do attention pixels,
// blocks [NATT, NATT+GSAMP) do loss row p = blockIdx.x - NATT.
__global__ __launch_bounds__(256) void attn_loss_kernel(const float* __restrict__ proto) {
    int b = blockIdx.y;
    int tid = threadIdx.x;

    if (blockIdx.x >= NATT) {
        // ---------------- loss part ----------------
        int p = blockIdx.x - NATT;
        int g = min(GSAMP, g_nkeep[b]);
        if (p >= g) return;
        __shared__ float sy[GSAMP][GDIM];
        __shared__ float sx[GSAMP][GDIM];
        for (int t = tid; t < GSAMP * GDIM; t += 256) {
            int k = t / GDIM, i = t % GDIM;
            sy[k][i] = g_g64y[b][k][i];
            sx[k][i] = g_g64x[b][k][i];
        }
        __syncthreads();
        int warp = tid >> 5, lane = tid & 31;
        const float* gyp = sy[p];
        const float* gxp = sx[p];
        int ip = g_perm[b][p];
        for (int q = warp; q < g; q += 8) {
            const float* gyq = sy[q];
            const float* gxq = sx[q];
            float inter = 0.0f, uni = 0.0f;
            for (int px = lane; px < GDIM * GDIM; px += 32) {
                int y = px >> 6, x = px & 63;
                float a = gyp[y] * gxp[x];
                float c = gyq[y] * gxq[x];
                inter += fminf(a, c);
                uni += fmaxf(a, c);
            }
#pragma unroll
            for (int o = 16; o > 0; o >>= 1) {
                inter += __shfl_down_sync(0xFFFFFFFFu, inter, o);
                uni   += __shfl_down_sync(0xFFFFFFFFu, uni, o);
            }
            if (lane == 0) {
                float giou = inter / (uni + EPSV);
                float pred = g_iou[b][ip][g_perm[b][q]];
                float d = pred - giou;
                atomicAdd(&g_acc_loss,
                          (unsigned long long)((double)(d * d) * SCALE_L + 0.5));
            }
        }
        return;
    }

    // ---------------- attention part ----------------
    int nk = g_nkeep[b];
    __shared__ int s_permk[MAXDET];
    __shared__ float s_mask[MAXDET * MDIM];
    __shared__ float s_conf[MAXDET];
    if (tid < nk) {
        int pk = g_perm[b][tid];
        s_permk[tid] = pk;
        s_conf[tid] = g_conf_k[b][pk];
    }
    __syncthreads();
    for (int t = tid; t < nk * MDIM; t += 256)
        s_mask[t] = g_mask_k[b][s_permk[t >> 5]][t & 31];
    __syncthreads();
    int p = blockIdx.x * 256 + tid;
    if (p >= PHW * PHW) return;
    int y = p / PHW, x = p % PHW;
    const float4* pp =
        reinterpret_cast<const float4*>(proto + (((size_t)b * PHW + y) * PHW + x) * MDIM);
    float4 pr[8];
#pragma unroll
    for (int i = 0; i < 8; i++) pr[i] = pp[i];
    float s1 = 0.0f, s2 = 0.0f;
    const float* gyb = &g_gy[b][0][0];
    const float* gxb = &g_gx[b][0][0];
    for (int k = 0; k < nk; k++) {
        const float4* mk = reinterpret_cast<const float4*>(&s_mask[k * MDIM]);
        float dot = 0.0f;
#pragma unroll
        for (int i = 0; i < 8; i++) {
            float4 m = mk[i];
            dot = fmaf(pr[i].x, m.x, dot);
            dot = fmaf(pr[i].y, m.y, dot);
            dot = fmaf(pr[i].z, m.z, dot);
            dot = fmaf(pr[i].w, m.w, dot);
        }
        float sg = __fdividef(1.0f, 1.0f + __expf(-dot));
        float mv = sg * __ldg(gyb + k * PHW + y) * __ldg(gxb + k * PHW + x) * s_conf[k];
        s1 += mv;
        s2 = fmaf(mv, mv, s2);
    }
    g_final[b][p] = 1.0f - s2 / (s1 + EPSV);
}

// --------- fused resize + total/wmean/variance (one pass) ------------------
__device__ __forceinline__ void resize_coords(int y, int x, int& y0, int& y1,
                                              int& x0, int& x1, float& wy, float& wx) {
    const float S = (float)PHW / (float)IMG;
    float sy = (y + 0.5f) * S - 0.5f;
    float sx = (x + 0.5f) * S - 0.5f;
    float fy = floorf(sy), fx = floorf(sx);
    wy = sy - fy;
    wx = sx - fx;
    y0 = max((int)fy, 0); y1 = min((int)fy + 1, PHW - 1);
    x0 = max((int)fx, 0); x1 = min((int)fx + 1, PHW - 1);
}

__device__ __forceinline__ float bilerp(const float* fb, int y0, int y1, int x0,
                                        int x1, float wy, float wx) {
    float a = fb[y0 * PHW + x0], b = fb[y0 * PHW + x1];
    float c = fb[y1 * PHW + x0], d = fb[y1 * PHW + x1];
    float top = a + (b - a) * wx;
    float bot = c + (d - c) * wx;
    return top + (bot - top) * wy;
}

__global__ __launch_bounds__(256) void fusedvar_kernel(const float* __restrict__ original) {
    int p = blockIdx.x * blockDim.x + threadIdx.x;
    int tid = threadIdx.x;
    float acc = 0.0f;
    if (p < IMG * IMG) {
        int y = p >> 9, x = p & 511;
        int y0, y1, x0, x1; float wy, wx;
        resize_coords(y, x, y0, y1, x0, x1, wy, wx);
        float r[NB];
        float o0[NB], o1[NB], o2[NB];
        float tot = 0.0f, wm0 = 0.0f, wm1 = 0.0f, wm2 = 0.0f;
#pragma unroll
        for (int b = 0; b < NB; b++) {
            r[b] = bilerp(g_final[b], y0, y1, x0, x1, wy, wx);
            tot += r[b];
            size_t base = ((size_t)b * 3) * (IMG * IMG) + p;
            o0[b] = original[base];
            o1[b] = original[base + IMG * IMG];
            o2[b] = original[base + 2 * IMG * IMG];
            wm0 = fmaf(o0[b], r[b], wm0);
            wm1 = fmaf(o1[b], r[b], wm1);
            wm2 = fmaf(o2[b], r[b], wm2);
        }
        float tinv = 1.0f / (tot + EPSV);
#pragma unroll
        for (int b = 0; b < NB; b++) {
            float d0 = o0[b] - wm0;
            float d1 = o1[b] - wm1;
            float d2 = o2[b] - wm2;
            acc = fmaf((d0 * d0 + d1 * d1 + d2 * d2), r[b], acc);
        }
        acc *= tinv;
    }
    // block reduce
    for (int o = 16; o > 0; o >>= 1) acc += __shfl_down_sync(0xFFFFFFFFu, acc, o);
    __shared__ float rs[8];
    int w = tid >> 5;
    if ((tid & 31) == 0) rs[w] = acc;
    __syncthreads();
    if (tid == 0) {
        float s = 0.0f;
#pragma unroll
        for (int i = 0; i < 8; i++) s += rs[i];
        atomicAdd(&g_acc_var, (unsigned long long)((double)s * SCALE_V + 0.5));
    }
}

// ------------------------------ finalize -----------------------------------
__global__ void finalize_kernel(float* __restrict__ out) {
    out[0] = (float)((double)g_acc_var / SCALE_V);
    out[1] = (float)((double)g_acc_loss / SCALE_L);
}

// ------------------------------ launcher -----------------------------------
extern "C" void kernel_launch(void* const* d_in, const int* in_sizes, int n_in,
                              void* d_out, int out_size) {
    const float* original = (const float*)d_in[0];
    const float* loc      = (const float*)d_in[1];
    const float* conf     = (const float*)d_in[2];
    const float* mask     = (const float*)d_in[3];
    const float* proto    = (const float*)d_in[4];
    const float* W1       = (const float*)d_in[5];
    const float* b1       = (const float*)d_in[6];
    const float* W2       = (const float*)d_in[7];
    const float* b2       = (const float*)d_in[8];
    float* out = (float*)d_out;

    topk_kernel<<<NB, 1024>>>(conf, loc, mask, W1, b1);
    mlp_kernel<<<dim3((TK + 15) / 16, (TK + 15) / 16, NB), 256>>>(W2, b2);
    nms_kernel<<<NB, 256>>>();
    attn_loss_kernel<<<dim3(NATT + GSAMP, NB), 256>>>(proto);
    fusedvar_kernel<<<(IMG * IMG) / 256, 256>>>(original);
    finalize_kernel<<<1, 1>>>(out);
}

// round 11
// speedup vs baseline: 2.7215x; 1.1070x over previous
#include <cuda_runtime.h>
#include <math.h>

#define NB 8
#define NP 19248
#define MDIM 32
#define TK 200
#define PHW 138
#define IMG 512
#define MIDW 64
#define GSAMP 16
#define GDIM 64
#define EPSV 1e-6f
#define CONF_TH 0.05f
#define NMS_TH 0.5f
#define MAXDET 100

#define NATT2 149  /* ceil(PHW*PHW/128) */
#define NVALS 19   /* ceil(NP/1024) */

// ------------------------------ scratch ------------------------------------
__device__ float g_conf_k[NB][TK];
__device__ int   g_validk[NB][TK];
__device__ float g_loc_k[NB][TK][4];
__device__ float g_mask_k[NB][TK][MDIM];
__device__ float g_Atab[NB][TK][MIDW];
__device__ float g_Btab[NB][TK][MIDW];
__device__ float g_iou[NB][TK][TK];
__device__ int   g_ioumaxI[NB][TK];
__device__ float g_final[NB][PHW * PHW];
__device__ unsigned long long g_acc_var;
__device__ unsigned long long g_acc_loss;

#define SCALE_V 262144.0          /* 2^18 */
#define SCALE_L 1099511627776.0   /* 2^40 */

__device__ __forceinline__ unsigned enc_float(float v) {
    unsigned u = __float_as_uint(v);
    return (u & 0x80000000u) ? ~u : (u | 0x80000000u);
}

// ------------------- top-k + MLP factor tables (fused) ---------------------
__global__ __launch_bounds__(1024) void topk_kernel(const float* __restrict__ conf,
                                                    const float* __restrict__ loc,
                                                    const float* __restrict__ mask,
                                                    const float* __restrict__ W1,
                                                    const float* __restrict__ b1) {
    int b = blockIdx.x;
    int tid = threadIdx.x;
    const float* cp = conf + (size_t)b * NP * 2;

    __shared__ unsigned hist[256];
    __shared__ int wtot[8];
    __shared__ unsigned s_prefix;
    __shared__ int s_remaining;
    __shared__ int s_cnt;
    __shared__ unsigned long long cand[1024];
    __shared__ unsigned long long s_sorted[TK];
    __shared__ int s_idx[TK];
    __shared__ float s_loc[TK * 4];

    if (b == 0 && tid == 0) { g_acc_var = 0ull; g_acc_loss = 0ull; }
    if (tid == 0) { s_prefix = 0u; s_remaining = TK; }

    // single global sweep: encode all values into registers (0 = OOB sentinel)
    unsigned enc[NVALS];
#pragma unroll
    for (int p = 0; p < NVALS; p++) {
        int i = tid + p * 1024;
        unsigned e = 0u;
        if (i < NP) {
            float c1 = cp[i * 2 + 1];
            float s = (c1 > CONF_TH) ? c1 : -1.0f;
            e = enc_float(s);
        }
        enc[p] = e;
    }
    __syncthreads();

    int lane = tid & 31;
    for (int pass = 0; pass < 3; pass++) {
        if (tid < 256) hist[tid] = 0u;
        __syncthreads();
        unsigned prefix = s_prefix;
        int shift_bin = 24 - 8 * pass;
#pragma unroll
        for (int p = 0; p < NVALS; p++) {
            unsigned e = enc[p];
            if (e != 0u) {
                unsigned hi = (pass == 0) ? 0u : (e >> (shift_bin + 8));
                if (hi == prefix) atomicAdd(&hist[(e >> shift_bin) & 0xFFu], 1u);
            }
        }
        __syncthreads();
        int rem = s_remaining;
        int h = 0, sfxv = 0;
        if (tid < 256) {
            h = (int)hist[tid];
            sfxv = h;
#pragma unroll
            for (int off = 1; off < 32; off <<= 1) {
                int n = __shfl_down_sync(0xFFFFFFFFu, sfxv, off);
                if (lane + off < 32) sfxv += n;
            }
            if (lane == 0) wtot[tid >> 5] = sfxv;
        }
        __syncthreads();
        if (tid < 256) {
            int add = 0;
            for (int wg = (tid >> 5) + 1; wg < 8; wg++) add += wtot[wg];
            int sfx = sfxv + add;
            int nxt = sfx - h;
            if (sfx >= rem && nxt < rem) {
                s_prefix = (s_prefix << 8) | (unsigned)tid;
                s_remaining = rem - nxt;
            }
        }
        __syncthreads();
    }

    if (tid == 0) s_cnt = 0;
    __syncthreads();
    unsigned thr24 = s_prefix;
#pragma unroll
    for (int p = 0; p < NVALS; p++) {
        unsigned e = enc[p];
        if (e != 0u && (e >> 8) >= thr24) {
            int i = tid + p * 1024;
            int pos = atomicAdd(&s_cnt, 1);
            if (pos < 1024)
                cand[pos] = ((unsigned long long)e << 32) |
                            (unsigned long long)(0xFFFFFFFFu - (unsigned)i);
        }
    }
    __syncthreads();
    int cnt = min(s_cnt, 1024);

    // rank-select
    if (tid < cnt) {
        unsigned long long key = cand[tid];
        int rank = 0;
        for (int i = 0; i < cnt; i++) rank += (cand[i] > key) ? 1 : 0;
        if (rank < TK) s_sorted[rank] = key;
    }
    __syncthreads();

    if (tid < TK) {
        unsigned long long key = s_sorted[tid];
        unsigned e = (unsigned)(key >> 32);
        int idx = (int)(0xFFFFFFFFu - (unsigned)(key & 0xFFFFFFFFull));
        unsigned u = (e & 0x80000000u) ? (e ^ 0x80000000u) : ~e;
        float v = __uint_as_float(u);
        int val = (v > CONF_TH) ? 1 : 0;
        g_validk[b][tid] = val;
        g_conf_k[b][tid] = val ? v : 0.0f;
        g_ioumaxI[b][tid] = 0;
        s_idx[tid] = idx;
    }
    __syncthreads();

    for (int t = tid; t < TK * 4; t += 1024) {
        int k = t >> 2, d = t & 3;
        float v = loc[((size_t)b * NP + s_idx[k]) * 4 + d];
        g_loc_k[b][k][d] = v;
        s_loc[t] = v;
    }
    for (int t = tid; t < TK * MDIM; t += 1024) {
        int k = t >> 5, d = t & 31;
        g_mask_k[b][k][d] = mask[((size_t)b * NP + s_idx[k]) * MDIM + d];
    }
    __syncthreads();

    for (int t = tid; t < TK * MIDW; t += 1024) {
        int k = t / MIDW, h = t % MIDW;
        float l0 = s_loc[k * 4 + 0], l1 = s_loc[k * 4 + 1];
        float l2 = s_loc[k * 4 + 2], l3 = s_loc[k * 4 + 3];
        float a = fmaf(l3, W1[3 * MIDW + h],
                  fmaf(l2, W1[2 * MIDW + h],
                  fmaf(l1, W1[1 * MIDW + h], l0 * W1[h])));
        float bb = fmaf(l3, W1[7 * MIDW + h],
                   fmaf(l2, W1[6 * MIDW + h],
                   fmaf(l1, W1[5 * MIDW + h], l0 * W1[4 * MIDW + h]))) + b1[h];
        g_Atab[b][k][h] = a;
        g_Btab[b][k][h] = bb;
    }
}

// -------------------------- 200x200 IoU MLP + column max -------------------
__global__ void mlp_kernel(const float* __restrict__ W2, const float* __restrict__ b2) {
    int b = blockIdx.z;
    int jb = blockIdx.x * 16, ib = blockIdx.y * 16;
    __shared__ float As[16][MIDW + 1];
    __shared__ float Bs[16][MIDW + 1];
    __shared__ float w2s[MIDW];
    __shared__ float s_b2;
    __shared__ int s_vi[16], s_vj[16];
    int tid = threadIdx.x;
    for (int t = tid; t < 16 * MIDW; t += 256) {
        int r = t / MIDW, h = t % MIDW;
        As[r][h] = (jb + r < TK) ? g_Atab[b][jb + r][h] : 0.0f;
        Bs[r][h] = (ib + r < TK) ? g_Btab[b][ib + r][h] : 0.0f;
    }
    if (tid < MIDW) w2s[tid] = W2[tid];
    if (tid == 0) s_b2 = b2[0];
    if (tid < 16) {
        s_vj[tid] = (jb + tid < TK) ? g_validk[b][jb + tid] : 0;
        s_vi[tid] = (ib + tid < TK) ? g_validk[b][ib + tid] : 0;
    }
    __syncthreads();
    int tj = tid & 15, ti = tid >> 4;
    int i = ib + ti, j = jb + tj;
    if (i < TK && j < TK) {
        float acc = s_b2;
#pragma unroll
        for (int h = 0; h < MIDW; h++) {
            float s = As[tj][h] + Bs[ti][h];
            acc = fmaf(fmaxf(s, 0.0f), w2s[h], acc);
        }
        float iou = __fdividef(1.0f, 1.0f + __expf(-acc));
        g_iou[b][i][j] = iou;
        if (i < j && s_vi[ti] && s_vj[tj])
            atomicMax(&g_ioumaxI[b][j], __float_as_int(iou));
    }
}

// ---- attention + loss (NMS scan redone locally, gaussians inline) ---------
// grid (NATT2 + GSAMP, NB), block 256.
// blocks [0,NATT2): 128 pixels each (2 lanes per pixel, MDIM split in half).
// blocks [NATT2, NATT2+GSAMP): loss row p.
__global__ __launch_bounds__(256) void attn_loss_kernel(const float* __restrict__ proto) {
    int b = blockIdx.y;
    int tid = threadIdx.x;

    // ---- local NMS scan (deterministic, same result in every block) ----
    __shared__ int s_perm[TK];
    __shared__ int wsum[8];
    __shared__ int s_nk;
    {
        int keep = 0;
        if (tid < TK) {
            int valid = g_validk[b][tid];
            float m = __int_as_float(g_ioumaxI[b][tid]);
            keep = (valid && m <= NMS_TH) ? 1 : 0;
        }
        int lane = tid & 31, wid = tid >> 5;
        int v = keep;
#pragma unroll
        for (int o = 1; o < 32; o <<= 1) {
            int n = __shfl_up_sync(0xFFFFFFFFu, v, o);
            if (lane >= o) v += n;
        }
        if (lane == 31) wsum[wid] = v;
        __syncthreads();
        if (tid < 8) {
            int w = wsum[tid];
#pragma unroll
            for (int o = 1; o < 8; o <<= 1) {
                int n = __shfl_up_sync(0xFFu, w, o);
                if ((int)tid >= o) w += n;
            }
            wsum[tid] = w;
        }
        __syncthreads();
        int incl = v + (wid ? wsum[wid - 1] : 0);
        int total = wsum[7];
        int nk = min(total, MAXDET);
        int keep2 = keep && (incl <= MAXDET);
        int incl2 = min(incl, MAXDET);
        if (tid == 0) s_nk = nk;
        if (tid < TK) {
            int pos = keep2 ? (incl2 - 1) : (nk + tid - incl2);
            s_perm[pos] = tid;
        }
        __syncthreads();
    }
    int nk = s_nk;

    if (blockIdx.x >= NATT2) {
        // -------------------- loss part --------------------
        int p = blockIdx.x - NATT2;
        int g = min(GSAMP, nk);
        if (p >= g) return;
        __shared__ __align__(16) float sy[GSAMP][GDIM];
        __shared__ __align__(16) float sx[GSAMP][GDIM];
        for (int t = tid; t < g * GDIM; t += 256) {
            int k = t >> 6, i = t & 63;
            int pk = s_perm[k];
            float cx = g_loc_k[b][pk][0], cy = g_loc_k[b][pk][1];
            float bw = g_loc_k[b][pk][2], bh = g_loc_k[b][pk][3];
            float s = (i + 0.5f) / (float)GDIM;
            float ty = (s - cy) / (bh * 0.5f + EPSV);
            float tx = (s - cx) / (bw * 0.5f + EPSV);
            sy[k][i] = __expf(-0.5f * ty * ty);
            sx[k][i] = __expf(-0.5f * tx * tx);
        }
        __syncthreads();
        int warp = tid >> 5, lane = tid & 31;
        const float* gyp = sy[p];
        const float* gxp = sx[p];
        int ip = s_perm[p];
        for (int q = warp; q < g; q += 8) {
            const float* gyq = sy[q];
            const float* gxq = sx[q];
            float inter = 0.0f, uni = 0.0f;
            for (int px = lane; px < GDIM * GDIM; px += 32) {
                int y = px >> 6, x = px & 63;
                float a = gyp[y] * gxp[x];
                float c = gyq[y] * gxq[x];
                inter += fminf(a, c);
                uni += fmaxf(a, c);
            }
#pragma unroll
            for (int o = 16; o > 0; o >>= 1) {
                inter += __shfl_down_sync(0xFFFFFFFFu, inter, o);
                uni   += __shfl_down_sync(0xFFFFFFFFu, uni, o);
            }
            if (lane == 0) {
                float giou = inter / (uni + EPSV);
                float pred = g_iou[b][ip][s_perm[q]];
                float d = pred - giou;
                atomicAdd(&g_acc_loss,
                          (unsigned long long)((double)(d * d) * SCALE_L + 0.5));
            }
        }
        return;
    }

    // -------------------- attention part --------------------
    __shared__ __align__(16) float s_mask[MAXDET * MDIM];
    __shared__ float s_cx[MAXDET], s_cy[MAXDET];
    __shared__ float s_iw[MAXDET], s_ih[MAXDET];
    __shared__ float s_cf[MAXDET];
    if (tid < nk) {
        int pk = s_perm[tid];
        s_cx[tid] = g_loc_k[b][pk][0];
        s_cy[tid] = g_loc_k[b][pk][1];
        s_iw[tid] = 1.0f / (g_loc_k[b][pk][2] * 0.5f + EPSV);
        s_ih[tid] = 1.0f / (g_loc_k[b][pk][3] * 0.5f + EPSV);
        s_cf[tid] = g_conf_k[b][pk];
    }
    __syncthreads();
    for (int t = tid; t < nk * MDIM; t += 256)
        s_mask[t] = g_mask_k[b][s_perm[t >> 5]][t & 31];
    __syncthreads();

    int pix = blockIdx.x * 128 + (tid >> 1);
    int half = tid & 1;
    bool live = pix < PHW * PHW;
    int pixc = live ? pix : 0;
    int y = pixc / PHW, x = pixc % PHW;
    float ys = (y + 0.5f) / (float)PHW;
    float xs = (x + 0.5f) / (float)PHW;
    const float4* pp = reinterpret_cast<const float4*>(
        proto + ((size_t)b * (PHW * PHW) + pixc) * MDIM + half * 16);
    float4 pr[4];
#pragma unroll
    for (int i = 0; i < 4; i++) pr[i] = pp[i];

    float s1 = 0.0f, s2 = 0.0f;
    for (int k = 0; k < nk; k++) {
        const float4* mk = reinterpret_cast<const float4*>(&s_mask[k * MDIM + half * 16]);
        float pd = 0.0f;
#pragma unroll
        for (int i = 0; i < 4; i++) {
            float4 m = mk[i];
            pd = fmaf(pr[i].x, m.x, pd);
            pd = fmaf(pr[i].y, m.y, pd);
            pd = fmaf(pr[i].z, m.z, pd);
            pd = fmaf(pr[i].w, m.w, pd);
        }
        float dot = pd + __shfl_xor_sync(0xFFFFFFFFu, pd, 1);
        float sg = __fdividef(1.0f, 1.0f + __expf(-dot));
        float ty = (ys - s_cy[k]) * s_ih[k];
        float tx = (xs - s_cx[k]) * s_iw[k];
        float g = __expf(-0.5f * fmaf(ty, ty, tx * tx));
        float mv = sg * g * s_cf[k];
        s1 += mv;
        s2 = fmaf(mv, mv, s2);
    }
    if (live && half == 0)
        g_final[b][pix] = 1.0f - s2 / (s1 + EPSV);
}

// --------- fused resize + total/wmean/variance (one pass) ------------------
__device__ __forceinline__ void resize_coords(int y, int x, int& y0, int& y1,
                                              int& x0, int& x1, float& wy, float& wx) {
    const float S = (float)PHW / (float)IMG;
    float sy = (y + 0.5f) * S - 0.5f;
    float sx = (x + 0.5f) * S - 0.5f;
    float fy = floorf(sy), fx = floorf(sx);
    wy = sy - fy;
    wx = sx - fx;
    y0 = max((int)fy, 0); y1 = min((int)fy + 1, PHW - 1);
    x0 = max((int)fx, 0); x1 = min((int)fx + 1, PHW - 1);
}

__device__ __forceinline__ float bilerp(const float* fb, int y0, int y1, int x0,
                                        int x1, float wy, float wx) {
    float a = fb[y0 * PHW + x0], b = fb[y0 * PHW + x1];
    float c = fb[y1 * PHW + x0], d = fb[y1 * PHW + x1];
    float top = a + (b - a) * wx;
    float bot = c + (d - c) * wx;
    return top + (bot - top) * wy;
}

__global__ __launch_bounds__(256) void fusedvar_kernel(const float* __restrict__ original) {
    int p = blockIdx.x * blockDim.x + threadIdx.x;
    int tid = threadIdx.x;
    float acc = 0.0f;
    if (p < IMG * IMG) {
        int y = p >> 9, x = p & 511;
        int y0, y1, x0, x1; float wy, wx;
        resize_coords(y, x, y0, y1, x0, x1, wy, wx);
        float r[NB];
        float o0[NB], o1[NB], o2[NB];
        float tot = 0.0f, wm0 = 0.0f, wm1 = 0.0f, wm2 = 0.0f;
#pragma unroll
        for (int b = 0; b < NB; b++) {
            r[b] = bilerp(g_final[b], y0, y1, x0, x1, wy, wx);
            tot += r[b];
            size_t base = ((size_t)b * 3) * (IMG * IMG) + p;
            o0[b] = original[base];
            o1[b] = original[base + IMG * IMG];
            o2[b] = original[base + 2 * IMG * IMG];
            wm0 = fmaf(o0[b], r[b], wm0);
            wm1 = fmaf(o1[b], r[b], wm1);
            wm2 = fmaf(o2[b], r[b], wm2);
        }
        float tinv = 1.0f / (tot + EPSV);
#pragma unroll
        for (int b = 0; b < NB; b++) {
            float d0 = o0[b] - wm0;
            float d1 = o1[b] - wm1;
            float d2 = o2[b] - wm2;
            acc = fmaf((d0 * d0 + d1 * d1 + d2 * d2), r[b], acc);
        }
        acc *= tinv;
    }
    for (int o = 16; o > 0; o >>= 1) acc += __shfl_down_sync(0xFFFFFFFFu, acc, o);
    __shared__ float rs[8];
    int w = tid >> 5;
    if ((tid & 31) == 0) rs[w] = acc;
    __syncthreads();
    if (tid == 0) {
        float s = 0.0f;
#pragma unroll
        for (int i = 0; i < 8; i++) s += rs[i];
        atomicAdd(&g_acc_var, (unsigned long long)((double)s * SCALE_V + 0.5));
    }
}

// ------------------------------ finalize -----------------------------------
__global__ void finalize_kernel(float* __restrict__ out) {
    out[0] = (float)((double)g_acc_var / SCALE_V);
    out[1] = (float)((double)g_acc_loss / SCALE_L);
}

// ------------------------------ launcher -----------------------------------
extern "C" void kernel_launch(void* const* d_in, const int* in_sizes, int n_in,
                              void* d_out, int out_size) {
    const float* original = (const float*)d_in[0];
    const float* loc      = (const float*)d_in[1];
    const float* conf     = (const float*)d_in[2];
    const float* mask     = (const float*)d_in[3];
    const float* proto    = (const float*)d_in[4];
    const float* W1       = (const float*)d_in[5];
    const float* b1       = (const float*)d_in[6];
    const float* W2       = (const float*)d_in[7];
    const float* b2       = (const float*)d_in[8];
    float* out = (float*)d_out;

    topk_kernel<<<NB, 1024>>>(conf, loc, mask, W1, b1);
    mlp_kernel<<<dim3((TK + 15) / 16, (TK + 15) / 16, NB), 256>>>(W2, b2);
    attn_loss_kernel<<<dim3(NATT2 + GSAMP, NB), 256>>>(proto);
    fusedvar_kernel<<<(IMG * IMG) / 256, 256>>>(original);
    finalize_kernel<<<1, 1>>>(out);
}